// round 8
// baseline (speedup 1.0000x reference)
#include <cuda_runtime.h>
#include <cuda_bf16.h>
#include <math_constants.h>
#include <cstdint>

#define BB 32
#define CC 9
#define TT 4096
#define NC 512
#define CD 64
#define KTOT 192          // hi | lo | hi split-K
#define MBLK 128          // positions per block
#define KP_B 400          // padded SMEM row stride in bytes (200 bf16)
#define CROWS 128         // codes per chunk (4 chunks)

#define OFF_IDX ((size_t)BB * TT * CD)
#define OFF_PH  (OFF_IDX + (size_t)BB * TT)

// SMEM map for quant kernel (bytes)
#define SM_A    0u
#define SM_B0   51200u
#define SM_B1   102400u
#define SM_CN   153600u
#define SM_RBV  155648u   // float [128][2] per-nwarp best
#define SM_RBI  156672u   // int   [128][2] per-nwarp idx
#define SM_IDX  157696u   // int   [128]
#define SMEMSZ  158208    // 1 CTA/SM

// ---------------- global scratch ----------------
__device__ float g_phase[BB * CC * TT];
__device__ __align__(16) __nv_bfloat16 g_B[NC * KTOT];   // segs (hi,hi,lo)
__device__ float g_cn[NC];

__device__ __forceinline__ uint32_t smem_to_u32(const void* p) {
    uint32_t a;
    asm("{ .reg .u64 t; cvta.to.shared.u64 t, %1; cvt.u32.u64 %0, t; }"
        : "=r"(a) : "l"(p));
    return a;
}

#define LDSM_X4(r0, r1, r2, r3, addr) \
    asm volatile("ldmatrix.sync.aligned.m8n8.x4.shared.b16 {%0,%1,%2,%3}, [%4];" \
                 : "=r"(r0), "=r"(r1), "=r"(r2), "=r"(r3) : "r"(addr))

#define MMA16816(d, a, b0, b1) \
    asm volatile("mma.sync.aligned.m16n8k16.row.col.f32.bf16.bf16.f32 " \
                 "{%0,%1,%2,%3}, {%4,%5,%6,%7}, {%8,%9}, {%0,%1,%2,%3};" \
                 : "+f"((d)[0]), "+f"((d)[1]), "+f"((d)[2]), "+f"((d)[3]) \
                 : "r"((a)[0]), "r"((a)[1]), "r"((a)[2]), "r"((a)[3]), \
                   "r"(b0), "r"(b1))

#define CP_ASYNC16(saddr, gptr) \
    asm volatile("cp.async.cg.shared.global [%0], [%1], 16;" \
                 :: "r"(saddr), "l"(gptr) : "memory")
#define CP_COMMIT() asm volatile("cp.async.commit_group;" ::: "memory")
#define CP_WAIT(n)  asm volatile("cp.async.wait_group %0;" :: "n"(n) : "memory")

__device__ __forceinline__ float2 cmulf(float2 a, float2 b) {
    return make_float2(a.x * b.x - a.y * b.y, a.x * b.y + a.y * b.x);
}
__device__ __forceinline__ float2 f2add(float2 a, float2 b) {
    return make_float2(a.x + b.x, a.y + b.y);
}
__device__ __forceinline__ float2 f2sub(float2 a, float2 b) {
    return make_float2(a.x - b.x, a.y - b.y);
}

__device__ __forceinline__ void split_pack(float v0, float v1,
                                           uint32_t& hp, uint32_t& lp) {
    __nv_bfloat16 h0 = __float2bfloat16(v0), h1 = __float2bfloat16(v1);
    __nv_bfloat16 l0 = __float2bfloat16(v0 - __bfloat162float(h0));
    __nv_bfloat16 l1 = __float2bfloat16(v1 - __bfloat162float(h1));
    hp = ((uint32_t)__bfloat16_as_ushort(h1) << 16) | __bfloat16_as_ushort(h0);
    lp = ((uint32_t)__bfloat16_as_ushort(l1) << 16) | __bfloat16_as_ushort(l0);
}

// ---------------- kernel 1: radix-4 FFT phase + fused codebook convert ----
// blocks [0, 288): one (b,c) row each (512 thr). blocks [288, 320): convert.
__global__ void fft_conv_kernel(const float* __restrict__ imu,
                                const float* __restrict__ cb) {
    const int tid = threadIdx.x;

    if (blockIdx.x >= BB * CC) {
        // ---- codebook convert: warp per code (16 warps) ----
        const int wid = tid >> 5, lane = tid & 31;
        const int c = (blockIdx.x - BB * CC) * 16 + wid;
        const float2 v = ((const float2*)(cb + (size_t)c * CD))[lane];
        float n = v.x * v.x + v.y * v.y;
        uint32_t hp, lp;
        split_pack(v.x, v.y, hp, lp);
        uint32_t* row32 = (uint32_t*)(g_B + (size_t)c * KTOT);
        row32[lane] = hp;
        row32[32 + lane] = hp;
        row32[64 + lane] = lp;
#pragma unroll
        for (int off = 16; off >= 1; off >>= 1)
            n += __shfl_xor_sync(0xffffffffu, n, off);
        if (lane == 0) g_cn[c] = n;
        return;
    }

    extern __shared__ float2 dsh[];
    float2* s = dsh;            // 4096
    float2* tw = dsh + TT;      // 4096: tw[k] = exp(-2*pi*i*k/4096)
    const int row = blockIdx.x;
    const float* x = imu + (size_t)row * TT;

    for (int k = tid; k < TT; k += 512) {
        float sn, cs;
        sincosf(-(float)CUDART_PI_F * (float)k / 2048.0f, &sn, &cs);
        tw[k] = make_float2(cs, sn);
    }
    for (int t = tid; t < TT; t += 512)
        s[t] = make_float2(x[t], 0.0f);
    __syncthreads();

    // Forward radix-4 DIF: natural in, base-4 digit-reversed out.
#pragma unroll
    for (int ls = 10; ls >= 0; ls -= 2) {
        const int L = 1 << ls;
        const int m = 1024 >> ls;
        for (int i = tid; i < 1024; i += 512) {
            const int j = i & (L - 1);
            const int i0 = ((i >> ls) << (ls + 2)) + j;
            float2 a = s[i0], b = s[i0 + L], c = s[i0 + 2 * L], d = s[i0 + 3 * L];
            float2 t0 = f2add(a, c), t1 = f2sub(a, c);
            float2 t2 = f2add(b, d), t3 = f2sub(b, d);
            s[i0] = f2add(t0, t2);
            s[i0 + L] = cmulf(make_float2(t1.x + t3.y, t1.y - t3.x), tw[j * m]);
            s[i0 + 2 * L] = cmulf(f2sub(t0, t2), tw[2 * j * m]);
            s[i0 + 3 * L] = cmulf(make_float2(t1.x - t3.y, t1.y + t3.x), tw[3 * j * m]);
        }
        __syncthreads();
    }

    // Hilbert multiplier h[k] applied at base-4 digit-reversed slot.
    for (int p = tid; p < TT; p += 512) {
        const int r = (int)(__brev((unsigned)p) >> 20);         // 12-bit reverse
        const int k = ((r & 0x555) << 1) | ((r >> 1) & 0x555);  // swap bit pairs
        float h;
        if (k == 0 || k == TT / 2) h = 1.0f;
        else if (k < TT / 2)       h = 2.0f;
        else                       h = 0.0f;
        s[p].x *= h;
        s[p].y *= h;
    }
    __syncthreads();

    // Inverse radix-4 DIT: digit-reversed in, natural out (conj twiddles, no 1/N).
#pragma unroll
    for (int ls = 0; ls <= 10; ls += 2) {
        const int L = 1 << ls;
        const int m = 1024 >> ls;
        for (int i = tid; i < 1024; i += 512) {
            const int j = i & (L - 1);
            const int i0 = ((i >> ls) << (ls + 2)) + j;
            float2 w1 = tw[j * m], w2 = tw[2 * j * m], w3 = tw[3 * j * m];
            float2 A = s[i0];
            float2 Bv = cmulf(s[i0 + L],     make_float2(w1.x, -w1.y));
            float2 Cv = cmulf(s[i0 + 2 * L], make_float2(w2.x, -w2.y));
            float2 Dv = cmulf(s[i0 + 3 * L], make_float2(w3.x, -w3.y));
            float2 t0 = f2add(A, Cv), t1 = f2sub(A, Cv);
            float2 t2 = f2add(Bv, Dv), t3 = f2sub(Bv, Dv);
            s[i0] = f2add(t0, t2);
            s[i0 + L] = make_float2(t1.x - t3.y, t1.y + t3.x);
            s[i0 + 2 * L] = f2sub(t0, t2);
            s[i0 + 3 * L] = make_float2(t1.x + t3.y, t1.y - t3.x);
        }
        __syncthreads();
    }

    float* ph = g_phase + (size_t)row * TT;
    for (int t = tid; t < TT; t += 512)
        ph[t] = atan2f(s[t].y, s[t].x);
}

// ---------------- kernel 2: fused features + HMMA GEMM + argmin ----------
__device__ __forceinline__ void prefetch_chunk(uint32_t sdst, int ch, int tid) {
    const char* src = (const char*)g_B + (size_t)ch * CROWS * KTOT * 2;
#pragma unroll
    for (int it = 0; it < 12; ++it) {
        const int i = tid + it * 256;       // 3072 uint4 total
        const int r = i / 24, kq = i - r * 24;
        CP_ASYNC16(sdst + (uint32_t)r * KP_B + (uint32_t)kq * 16u,
                   src + (size_t)r * 384 + (size_t)kq * 16);
    }
    CP_COMMIT();
}

__global__ void __launch_bounds__(256, 1)
quant_kernel(const float* __restrict__ imu,
             const float* __restrict__ Wm,
             const float* __restrict__ bm,
             const float* __restrict__ Wp,
             const float* __restrict__ bp,
             const float* __restrict__ cb,
             float* __restrict__ out) {
    extern __shared__ char smem[];
    const uint32_t sbase = smem_to_u32(smem);
    const int tid = threadIdx.x;
    const int wid = tid >> 5;
    const int lane = tid & 31;
    const int pbase = blockIdx.x * MBLK;

    float* scn = (float*)(smem + SM_CN);
    float* rbv = (float*)(smem + SM_RBV);
    int* rbi = (int*)(smem + SM_RBI);
    int* sidx = (int*)(smem + SM_IDX);

    // start B pipeline before the heavy feature phase
    prefetch_chunk(sbase + SM_B0, 0, tid);
    prefetch_chunk(sbase + SM_B1, 1, tid);

    for (int i = tid; i < NC; i += 256) scn[i] = g_cn[i];

    // ---- features for 128 positions -> SMEM A (bf16 split)
    if (tid < MBLK) {
        const int p = pbase + tid;
        const int b = p >> 12;
        const int t = p & (TT - 1);

        const float* xb = imu + (size_t)b * CC * TT + t;
        float xc[9];
#pragma unroll
        for (int c = 0; c < 9; ++c) xc[c] = xb[c * TT];

        const float* phb = g_phase + (size_t)b * CC * TT + t;
        float pm = 0.0f;
#pragma unroll
        for (int c = 0; c < 9; ++c) pm += phb[c * TT];
        pm *= (1.0f / 9.0f);
        float sp, cp;
        sincosf(pm, &sp, &cp);
        out[OFF_PH + p] = pm;

        float f[64];
#pragma unroll
        for (int i = 0; i < 32; ++i) {
            float a = bm[i];
#pragma unroll
            for (int c = 0; c < 9; ++c) a += Wm[i * 9 + c] * xc[c];
            f[i] = a;
        }
        float comb[9];
#pragma unroll
        for (int c = 0; c < 7; ++c) comb[c] = xc[c];
        comb[7] = cp;
        comb[8] = sp;
#pragma unroll
        for (int i = 0; i < 32; ++i) {
            float a = bp[i];
#pragma unroll
            for (int c = 0; c < 9; ++c) a += Wp[i * 9 + c] * comb[c];
            f[32 + i] = a;
        }

        uint32_t* row32 = (uint32_t*)(smem + SM_A + (uint32_t)tid * KP_B);
#pragma unroll
        for (int q = 0; q < 32; ++q) {
            uint32_t hp, lp;
            split_pack(f[2 * q], f[2 * q + 1], hp, lp);
            row32[q] = hp;            // seg0: f_hi
            row32[32 + q] = lp;       // seg1: f_lo
            row32[64 + q] = hp;       // seg2: f_hi
        }
    }
    __syncthreads();   // A + cn visible

    // ---- GEMM + argmin. Warp grid: 4 m-warps (m32) x 2 n-warps (n32).
    const int wm = wid & 3;
    const int wn = wid >> 2;
    const int m0 = wm * 32;

    const int mgrp = lane >> 3;     // 0..3
    const int mrow = lane & 7;
    const uint32_t a_base = sbase + SM_A
        + (uint32_t)(m0 + mrow + 8 * (mgrp & 1)) * KP_B
        + (uint32_t)(8 * (mgrp >> 1)) * 2u;
    const uint32_t b_row_off = (uint32_t)(8 * (mgrp >> 1) + mrow) * KP_B
        + (uint32_t)(8 * (mgrp & 1)) * 2u;

    // ---- A fragments register-resident across all chunks (96 regs)
    uint32_t afr[2][12][4];
#pragma unroll
    for (int ks = 0; ks < 12; ++ks)
#pragma unroll
        for (int mt = 0; mt < 2; ++mt)
            LDSM_X4(afr[mt][ks][0], afr[mt][ks][1], afr[mt][ks][2], afr[mt][ks][3],
                    a_base + (uint32_t)mt * (16u * KP_B) + (uint32_t)ks * 32u);

    float best[4];
    int bidx[4];
#pragma unroll
    for (int i = 0; i < 4; ++i) { best[i] = CUDART_INF_F; bidx[i] = 0; }

#pragma unroll 1
    for (int ch = 0; ch < 4; ++ch) {
        if (ch < 3) { CP_WAIT(1); } else { CP_WAIT(0); }
        __syncthreads();            // chunk buffer complete for all warps

        const uint32_t sB = sbase + ((ch & 1) ? SM_B1 : SM_B0);

#pragma unroll 1
        for (int sub = 0; sub < 2; ++sub) {
            const uint32_t nbase = (uint32_t)(sub * 64 + wn * 32);
            float acc[2][4][4];
#pragma unroll
            for (int mt = 0; mt < 2; ++mt)
#pragma unroll
                for (int nt = 0; nt < 4; ++nt)
#pragma unroll
                    for (int q = 0; q < 4; ++q) acc[mt][nt][q] = 0.0f;

#pragma unroll
            for (int ks = 0; ks < 12; ++ks) {
                const uint32_t koff = (uint32_t)ks * 32u;
                uint32_t b0q[4], b1q[4];
                LDSM_X4(b0q[0], b0q[1], b0q[2], b0q[3],
                        sB + nbase * KP_B + b_row_off + koff);
                LDSM_X4(b1q[0], b1q[1], b1q[2], b1q[3],
                        sB + (nbase + 16u) * KP_B + b_row_off + koff);
#pragma unroll
                for (int mt = 0; mt < 2; ++mt) {
                    MMA16816(acc[mt][0], afr[mt][ks], b0q[0], b0q[1]);
                    MMA16816(acc[mt][1], afr[mt][ks], b0q[2], b0q[3]);
                    MMA16816(acc[mt][2], afr[mt][ks], b1q[0], b1q[1]);
                    MMA16816(acc[mt][3], afr[mt][ks], b1q[2], b1q[3]);
                }
            }

            // running argmin (codes strictly increasing -> first-min kept)
#pragma unroll
            for (int mt = 0; mt < 2; ++mt)
#pragma unroll
                for (int nt = 0; nt < 4; ++nt) {
                    const int c0 = ch * CROWS + (int)nbase + nt * 8 + (lane & 3) * 2;
                    const float n0v = scn[c0], n1v = scn[c0 + 1];
                    const float d0 = fmaf(-2.0f, acc[mt][nt][0], n0v);
                    const float d1 = fmaf(-2.0f, acc[mt][nt][1], n1v);
                    const float d2 = fmaf(-2.0f, acc[mt][nt][2], n0v);
                    const float d3 = fmaf(-2.0f, acc[mt][nt][3], n1v);
                    const int s0 = 2 * mt, s1 = 2 * mt + 1;
                    if (d0 < best[s0]) { best[s0] = d0; bidx[s0] = c0; }
                    if (d1 < best[s0]) { best[s0] = d1; bidx[s0] = c0 + 1; }
                    if (d2 < best[s1]) { best[s1] = d2; bidx[s1] = c0; }
                    if (d3 < best[s1]) { best[s1] = d3; bidx[s1] = c0 + 1; }
                }
        }

        __syncthreads();            // all warps done reading this buffer
        if (ch < 2) prefetch_chunk(sbase + ((ch & 1) ? SM_B1 : SM_B0),
                                   ch + 2, tid);
    }

    // reduce across the 4 lanes sharing each row (quad)
#pragma unroll
    for (int off = 1; off <= 2; off <<= 1) {
#pragma unroll
        for (int s = 0; s < 4; ++s) {
            float ob = __shfl_xor_sync(0xffffffffu, best[s], off);
            int oi = __shfl_xor_sync(0xffffffffu, bidx[s], off);
            if (ob < best[s] || (ob == best[s] && oi < bidx[s])) {
                best[s] = ob; bidx[s] = oi;
            }
        }
    }
    if ((lane & 3) == 0) {
        const int r = lane >> 2;
#pragma unroll
        for (int mt = 0; mt < 2; ++mt)
#pragma unroll
            for (int h = 0; h < 2; ++h) {
                const int row = m0 + mt * 16 + 8 * h + r;
                rbv[row * 2 + wn] = best[2 * mt + h];
                rbi[row * 2 + wn] = bidx[2 * mt + h];
            }
    }
    __syncthreads();

    // cross-nwarp reduce: one thread per row
    if (tid < MBLK) {
        float bv = rbv[tid * 2];
        int bi = rbi[tid * 2];
        const float ov = rbv[tid * 2 + 1];
        const int oi = rbi[tid * 2 + 1];
        if (ov < bv || (ov == bv && oi < bi)) { bv = ov; bi = oi; }
        sidx[tid] = bi;
        out[OFF_IDX + pbase + tid] = (float)bi;
    }
    __syncthreads();

    // quantized rows from fp32 codebook (L2-hot)
    const float4* cb4 = (const float4*)cb;
    for (int q = tid; q < MBLK * (CD / 4); q += 256) {
        const int pos = q >> 4;
        const int w = q & 15;
        ((float4*)(out + (size_t)(pbase + pos) * CD))[w] =
            cb4[(size_t)sidx[pos] * (CD / 4) + w];
    }
}

// ---------------- launch ----------------
extern "C" void kernel_launch(void* const* d_in, const int* in_sizes, int n_in,
                              void* d_out, int out_size) {
    const float* imu = (const float*)d_in[0];
    const float* Wm  = (const float*)d_in[1];
    const float* bm  = (const float*)d_in[2];
    const float* Wp  = (const float*)d_in[3];
    const float* bp  = (const float*)d_in[4];
    const float* cb  = (const float*)d_in[5];
    float* out = (float*)d_out;

    const int fft_smem = 2 * TT * (int)sizeof(float2);  // 64 KB
    cudaFuncSetAttribute(fft_conv_kernel,
                         cudaFuncAttributeMaxDynamicSharedMemorySize, fft_smem);
    fft_conv_kernel<<<BB * CC + NC / 16, 512, fft_smem>>>(imu, cb);

    cudaFuncSetAttribute(quant_kernel,
                         cudaFuncAttributeMaxDynamicSharedMemorySize, SMEMSZ);
    quant_kernel<<<(BB * TT) / MBLK, 256, SMEMSZ>>>(imu, Wm, bm, Wp, bp, cb, out);
}

// round 9
// speedup vs baseline: 1.2924x; 1.2924x over previous
#include <cuda_runtime.h>
#include <cuda_bf16.h>
#include <math_constants.h>
#include <cstdint>

#define BB 32
#define CC 9
#define TT 4096
#define NC 512
#define CD 64
#define KTOT 192          // hi | lo | hi split-K
#define MBLK 128          // positions per block
#define KP_B 400          // padded SMEM row stride in bytes (200 bf16)
#define CROWS 64          // codes per chunk (8 chunks)
#define NROWS (BB * CC)   // 288 real rows
#define NPAIR (NROWS / 2) // 144 packed FFTs

#define OFF_IDX ((size_t)BB * TT * CD)
#define OFF_PH  (OFF_IDX + (size_t)BB * TT)

// SMEM map for quant kernel (bytes)
#define SM_A    0u
#define SM_B0   51200u
#define SM_B1   76800u
#define SM_CN   102400u
#define SM_RBV  104448u   // float [128][4] per-warpcol best
#define SM_RBI  106496u   // int   [128][4] per-warpcol idx
#define SM_IDX  108544u   // int   [128]
#define SMEMSZ  109056    // 2 CTAs/SM

// ---------------- global scratch ----------------
__device__ float g_phase[BB * CC * TT];
__device__ __align__(16) __nv_bfloat16 g_B[NC * KTOT];   // segs (hi,hi,lo)
__device__ float g_cn[NC];

__device__ __forceinline__ uint32_t smem_to_u32(const void* p) {
    uint32_t a;
    asm("{ .reg .u64 t; cvta.to.shared.u64 t, %1; cvt.u32.u64 %0, t; }"
        : "=r"(a) : "l"(p));
    return a;
}

#define LDSM_X4(r0, r1, r2, r3, addr) \
    asm volatile("ldmatrix.sync.aligned.m8n8.x4.shared.b16 {%0,%1,%2,%3}, [%4];" \
                 : "=r"(r0), "=r"(r1), "=r"(r2), "=r"(r3) : "r"(addr))

#define MMA16816(d, a, b0, b1) \
    asm volatile("mma.sync.aligned.m16n8k16.row.col.f32.bf16.bf16.f32 " \
                 "{%0,%1,%2,%3}, {%4,%5,%6,%7}, {%8,%9}, {%0,%1,%2,%3};" \
                 : "+f"((d)[0]), "+f"((d)[1]), "+f"((d)[2]), "+f"((d)[3]) \
                 : "r"((a)[0]), "r"((a)[1]), "r"((a)[2]), "r"((a)[3]), \
                   "r"(b0), "r"(b1))

#define CP_ASYNC16(saddr, gptr) \
    asm volatile("cp.async.cg.shared.global [%0], [%1], 16;" \
                 :: "r"(saddr), "l"(gptr) : "memory")
#define CP_COMMIT() asm volatile("cp.async.commit_group;" ::: "memory")
#define CP_WAIT(n)  asm volatile("cp.async.wait_group %0;" :: "n"(n) : "memory")

__device__ __forceinline__ float2 cmulf(float2 a, float2 b) {
    return make_float2(a.x * b.x - a.y * b.y, a.x * b.y + a.y * b.x);
}
__device__ __forceinline__ float2 f2add(float2 a, float2 b) {
    return make_float2(a.x + b.x, a.y + b.y);
}
__device__ __forceinline__ float2 f2sub(float2 a, float2 b) {
    return make_float2(a.x - b.x, a.y - b.y);
}

__device__ __forceinline__ void split_pack(float v0, float v1,
                                           uint32_t& hp, uint32_t& lp) {
    __nv_bfloat16 h0 = __float2bfloat16(v0), h1 = __float2bfloat16(v1);
    __nv_bfloat16 l0 = __float2bfloat16(v0 - __bfloat162float(h0));
    __nv_bfloat16 l1 = __float2bfloat16(v1 - __bfloat162float(h1));
    hp = ((uint32_t)__bfloat16_as_ushort(h1) << 16) | __bfloat16_as_ushort(h0);
    lp = ((uint32_t)__bfloat16_as_ushort(l1) << 16) | __bfloat16_as_ushort(l0);
}

// ---------------- kernel 1: packed Hilbert FFT + fused codebook convert ----
// blocks [0, 144): two real rows packed as one complex FFT (512 thr).
// blocks [144, 176): codebook convert (16 warps each).
__global__ void fft_conv_kernel(const float* __restrict__ imu,
                                const float* __restrict__ cb) {
    const int tid = threadIdx.x;

    if (blockIdx.x >= NPAIR) {
        // ---- codebook convert: warp per code (16 warps) ----
        const int wid = tid >> 5, lane = tid & 31;
        const int c = (blockIdx.x - NPAIR) * 16 + wid;
        const float2 v = ((const float2*)(cb + (size_t)c * CD))[lane];
        float n = v.x * v.x + v.y * v.y;
        uint32_t hp, lp;
        split_pack(v.x, v.y, hp, lp);
        uint32_t* row32 = (uint32_t*)(g_B + (size_t)c * KTOT);
        row32[lane] = hp;
        row32[32 + lane] = hp;
        row32[64 + lane] = lp;
#pragma unroll
        for (int off = 16; off >= 1; off >>= 1)
            n += __shfl_xor_sync(0xffffffffu, n, off);
        if (lane == 0) g_cn[c] = n;
        return;
    }

    extern __shared__ float2 dsh[];
    float2* s = dsh;            // 4096
    float2* tw = dsh + TT;      // 4096: tw[k] = exp(-2*pi*i*k/4096)
    const float* x0 = imu + (size_t)(2 * blockIdx.x) * TT;
    const float* x1 = x0 + TT;

    for (int k = tid; k < TT; k += 512) {
        float sn, cs;
        sincosf(-(float)CUDART_PI_F * (float)k / 2048.0f, &sn, &cs);
        tw[k] = make_float2(cs, sn);
    }
    // pack two real rows into one complex signal
    for (int t = tid; t < TT; t += 512)
        s[t] = make_float2(x0[t], x1[t]);
    __syncthreads();

    // Forward radix-4 DIF: natural in, base-4 digit-reversed out.
#pragma unroll
    for (int ls = 10; ls >= 0; ls -= 2) {
        const int L = 1 << ls;
        const int m = 1024 >> ls;
        for (int i = tid; i < 1024; i += 512) {
            const int j = i & (L - 1);
            const int i0 = ((i >> ls) << (ls + 2)) + j;
            float2 a = s[i0], b = s[i0 + L], c = s[i0 + 2 * L], d = s[i0 + 3 * L];
            float2 t0 = f2add(a, c), t1 = f2sub(a, c);
            float2 t2 = f2add(b, d), t3 = f2sub(b, d);
            s[i0] = f2add(t0, t2);
            s[i0 + L] = cmulf(make_float2(t1.x + t3.y, t1.y - t3.x), tw[j * m]);
            s[i0 + 2 * L] = cmulf(f2sub(t0, t2), tw[2 * j * m]);
            s[i0 + 3 * L] = cmulf(make_float2(t1.x - t3.y, t1.y + t3.x), tw[3 * j * m]);
        }
        __syncthreads();
    }

    // Hilbert multiplier M[k] = -i*sgn(k) applied at base-4 digit-reversed slot.
    // k<N/2: (x,y)->(y,-x)  [*-i] ; k>N/2: (x,y)->(-y,x) [*+i] ; 0 at DC/Nyq.
    for (int p = tid; p < TT; p += 512) {
        const int r = (int)(__brev((unsigned)p) >> 20);         // 12-bit reverse
        const int k = ((r & 0x555) << 1) | ((r >> 1) & 0x555);  // swap bit pairs
        float2 v = s[p];
        if (k == 0 || k == TT / 2)  s[p] = make_float2(0.0f, 0.0f);
        else if (k < TT / 2)        s[p] = make_float2(v.y, -v.x);
        else                        s[p] = make_float2(-v.y, v.x);
    }
    __syncthreads();

    // Inverse radix-4 DIT: digit-reversed in, natural out (conj twiddles, no 1/N).
#pragma unroll
    for (int ls = 0; ls <= 10; ls += 2) {
        const int L = 1 << ls;
        const int m = 1024 >> ls;
        for (int i = tid; i < 1024; i += 512) {
            const int j = i & (L - 1);
            const int i0 = ((i >> ls) << (ls + 2)) + j;
            float2 w1 = tw[j * m], w2 = tw[2 * j * m], w3 = tw[3 * j * m];
            float2 A = s[i0];
            float2 Bv = cmulf(s[i0 + L],     make_float2(w1.x, -w1.y));
            float2 Cv = cmulf(s[i0 + 2 * L], make_float2(w2.x, -w2.y));
            float2 Dv = cmulf(s[i0 + 3 * L], make_float2(w3.x, -w3.y));
            float2 t0 = f2add(A, Cv), t1 = f2sub(A, Cv);
            float2 t2 = f2add(Bv, Dv), t3 = f2sub(Bv, Dv);
            s[i0] = f2add(t0, t2);
            s[i0 + L] = make_float2(t1.x - t3.y, t1.y + t3.x);
            s[i0 + 2 * L] = f2sub(t0, t2);
            s[i0 + 3 * L] = make_float2(t1.x + t3.y, t1.y - t3.x);
        }
        __syncthreads();
    }

    // phases: Re(analytic) = x exactly; Im = s/N (scale both by N instead)
    float* ph0 = g_phase + (size_t)(2 * blockIdx.x) * TT;
    float* ph1 = ph0 + TT;
    for (int t = tid; t < TT; t += 512) {
        const float2 v = s[t];
        ph0[t] = atan2f(v.x, 4096.0f * x0[t]);
        ph1[t] = atan2f(v.y, 4096.0f * x1[t]);
    }
}

// ---------------- kernel 2: fused features + HMMA GEMM + argmin ----------
__device__ __forceinline__ void prefetch_chunk(uint32_t sdst, int ch, int tid) {
    const char* src = (const char*)g_B + (size_t)ch * CROWS * KTOT * 2;
#pragma unroll
    for (int it = 0; it < 6; ++it) {
        const int i = tid + it * 256;       // 1536 uint4 total
        const int r = i / 24, kq = i - r * 24;
        CP_ASYNC16(sdst + (uint32_t)r * KP_B + (uint32_t)kq * 16u,
                   src + (size_t)r * 384 + (size_t)kq * 16);
    }
    CP_COMMIT();
}

__global__ void __launch_bounds__(256, 2)
quant_kernel(const float* __restrict__ imu,
             const float* __restrict__ Wm,
             const float* __restrict__ bm,
             const float* __restrict__ Wp,
             const float* __restrict__ bp,
             const float* __restrict__ cb,
             float* __restrict__ out) {
    extern __shared__ char smem[];
    const uint32_t sbase = smem_to_u32(smem);
    const int tid = threadIdx.x;
    const int wid = tid >> 5;
    const int lane = tid & 31;
    const int pbase = blockIdx.x * MBLK;

    float* scn = (float*)(smem + SM_CN);
    float* rbv = (float*)(smem + SM_RBV);
    int* rbi = (int*)(smem + SM_RBI);
    int* sidx = (int*)(smem + SM_IDX);

    // start B pipeline before the heavy feature phase
    prefetch_chunk(sbase + SM_B0, 0, tid);
    prefetch_chunk(sbase + SM_B1, 1, tid);

    for (int i = tid; i < NC; i += 256) scn[i] = g_cn[i];

    // ---- features for 128 positions -> SMEM A (bf16 split)
    if (tid < MBLK) {
        const int p = pbase + tid;
        const int b = p >> 12;
        const int t = p & (TT - 1);

        const float* xb = imu + (size_t)b * CC * TT + t;
        float xc[9];
#pragma unroll
        for (int c = 0; c < 9; ++c) xc[c] = xb[c * TT];

        const float* phb = g_phase + (size_t)b * CC * TT + t;
        float pm = 0.0f;
#pragma unroll
        for (int c = 0; c < 9; ++c) pm += phb[c * TT];
        pm *= (1.0f / 9.0f);
        float sp, cp;
        sincosf(pm, &sp, &cp);
        out[OFF_PH + p] = pm;

        float f[64];
#pragma unroll
        for (int i = 0; i < 32; ++i) {
            float a = bm[i];
#pragma unroll
            for (int c = 0; c < 9; ++c) a += Wm[i * 9 + c] * xc[c];
            f[i] = a;
        }
        float comb[9];
#pragma unroll
        for (int c = 0; c < 7; ++c) comb[c] = xc[c];
        comb[7] = cp;
        comb[8] = sp;
#pragma unroll
        for (int i = 0; i < 32; ++i) {
            float a = bp[i];
#pragma unroll
            for (int c = 0; c < 9; ++c) a += Wp[i * 9 + c] * comb[c];
            f[32 + i] = a;
        }

        uint32_t* row32 = (uint32_t*)(smem + SM_A + (uint32_t)tid * KP_B);
#pragma unroll
        for (int q = 0; q < 32; ++q) {
            uint32_t hp, lp;
            split_pack(f[2 * q], f[2 * q + 1], hp, lp);
            row32[q] = hp;            // seg0: f_hi
            row32[32 + q] = lp;       // seg1: f_lo
            row32[64 + q] = hp;       // seg2: f_hi
        }
    }
    __syncthreads();   // A + cn visible

    // ---- GEMM + argmin. Warp tile m64 x n16: wrow = wid&1, wcol = wid>>1.
    const int wrow = wid & 1;
    const int wcol = wid >> 1;
    const int m0 = wrow * 64;

    float best[8];
    int bidx[8];
#pragma unroll
    for (int i = 0; i < 8; ++i) { best[i] = CUDART_INF_F; bidx[i] = 0; }

    const int mgrp = lane >> 3;     // 0..3
    const int mrow = lane & 7;
    const uint32_t a_base = sbase + SM_A
        + (uint32_t)(m0 + mrow + 8 * (mgrp & 1)) * KP_B
        + (uint32_t)(8 * (mgrp >> 1)) * 2u;
    const uint32_t b_off = (uint32_t)(wcol * 16) * KP_B
        + (uint32_t)(8 * (mgrp >> 1) + mrow) * KP_B
        + (uint32_t)(8 * (mgrp & 1)) * 2u;

#pragma unroll 1
    for (int ch = 0; ch < 8; ++ch) {
        if (ch < 7) { CP_WAIT(1); } else { CP_WAIT(0); }
        __syncthreads();            // chunk buffer complete for all warps

        const uint32_t sB = sbase + ((ch & 1) ? SM_B1 : SM_B0);

        float acc[4][2][4];
#pragma unroll
        for (int mt = 0; mt < 4; ++mt)
#pragma unroll
            for (int j = 0; j < 2; ++j)
#pragma unroll
                for (int q = 0; q < 4; ++q) acc[mt][j][q] = 0.0f;

#pragma unroll
        for (int ks = 0; ks < 12; ++ks) {
            const uint32_t koff = (uint32_t)ks * 32u;
            uint32_t bq0, bq1, bq2, bq3;
            LDSM_X4(bq0, bq1, bq2, bq3, sB + b_off + koff);
#pragma unroll
            for (int mt = 0; mt < 4; ++mt) {
                uint32_t a[4];
                LDSM_X4(a[0], a[1], a[2], a[3],
                        a_base + (uint32_t)mt * (16u * KP_B) + koff);
                MMA16816(acc[mt][0], a, bq0, bq1);
                MMA16816(acc[mt][1], a, bq2, bq3);
            }
        }

        // running argmin (codes strictly increasing -> first-min kept)
#pragma unroll
        for (int mt = 0; mt < 4; ++mt)
#pragma unroll
            for (int j = 0; j < 2; ++j) {
                const int c0 = ch * CROWS + wcol * 16 + j * 8 + (lane & 3) * 2;
                const float n0v = scn[c0], n1v = scn[c0 + 1];
                const float d0 = fmaf(-2.0f, acc[mt][j][0], n0v);
                const float d1 = fmaf(-2.0f, acc[mt][j][1], n1v);
                const float d2 = fmaf(-2.0f, acc[mt][j][2], n0v);
                const float d3 = fmaf(-2.0f, acc[mt][j][3], n1v);
                const int s0 = 2 * mt, s1 = 2 * mt + 1;
                if (d0 < best[s0]) { best[s0] = d0; bidx[s0] = c0; }
                if (d1 < best[s0]) { best[s0] = d1; bidx[s0] = c0 + 1; }
                if (d2 < best[s1]) { best[s1] = d2; bidx[s1] = c0; }
                if (d3 < best[s1]) { best[s1] = d3; bidx[s1] = c0 + 1; }
            }

        __syncthreads();            // all warps done reading this buffer
        if (ch < 6) prefetch_chunk(sbase + ((ch & 1) ? SM_B1 : SM_B0),
                                   ch + 2, tid);
    }

    // reduce across the 4 lanes sharing each row (quad)
#pragma unroll
    for (int off = 1; off <= 2; off <<= 1) {
#pragma unroll
        for (int s = 0; s < 8; ++s) {
            float ob = __shfl_xor_sync(0xffffffffu, best[s], off);
            int oi = __shfl_xor_sync(0xffffffffu, bidx[s], off);
            if (ob < best[s] || (ob == best[s] && oi < bidx[s])) {
                best[s] = ob; bidx[s] = oi;
            }
        }
    }
    if ((lane & 3) == 0) {
        const int r = lane >> 2;
#pragma unroll
        for (int mt = 0; mt < 4; ++mt)
#pragma unroll
            for (int h = 0; h < 2; ++h) {
                const int row = m0 + mt * 16 + 8 * h + r;
                rbv[row * 4 + wcol] = best[2 * mt + h];
                rbi[row * 4 + wcol] = bidx[2 * mt + h];
            }
    }
    __syncthreads();

    // cross-warpcol reduce: one thread per row
    if (tid < MBLK) {
        float bv = rbv[tid * 4];
        int bi = rbi[tid * 4];
#pragma unroll
        for (int w = 1; w < 4; ++w) {
            const float ov = rbv[tid * 4 + w];
            const int oi = rbi[tid * 4 + w];
            if (ov < bv || (ov == bv && oi < bi)) { bv = ov; bi = oi; }
        }
        sidx[tid] = bi;
        out[OFF_IDX + pbase + tid] = (float)bi;
    }
    __syncthreads();

    // quantized rows from fp32 codebook (L2-hot)
    const float4* cb4 = (const float4*)cb;
    for (int q = tid; q < MBLK * (CD / 4); q += 256) {
        const int pos = q >> 4;
        const int w = q & 15;
        ((float4*)(out + (size_t)(pbase + pos) * CD))[w] =
            cb4[(size_t)sidx[pos] * (CD / 4) + w];
    }
}

// ---------------- launch ----------------
extern "C" void kernel_launch(void* const* d_in, const int* in_sizes, int n_in,
                              void* d_out, int out_size) {
    const float* imu = (const float*)d_in[0];
    const float* Wm  = (const float*)d_in[1];
    const float* bm  = (const float*)d_in[2];
    const float* Wp  = (const float*)d_in[3];
    const float* bp  = (const float*)d_in[4];
    const float* cb  = (const float*)d_in[5];
    float* out = (float*)d_out;

    const int fft_smem = 2 * TT * (int)sizeof(float2);  // 64 KB
    cudaFuncSetAttribute(fft_conv_kernel,
                         cudaFuncAttributeMaxDynamicSharedMemorySize, fft_smem);
    fft_conv_kernel<<<NPAIR + NC / 16, 512, fft_smem>>>(imu, cb);

    cudaFuncSetAttribute(quant_kernel,
                         cudaFuncAttributeMaxDynamicSharedMemorySize, SMEMSZ);
    quant_kernel<<<(BB * TT) / MBLK, 256, SMEMSZ>>>(imu, Wm, bm, Wp, bp, cb, out);
}

// round 10
// speedup vs baseline: 1.4091x; 1.0903x over previous
#include <cuda_runtime.h>
#include <cuda_bf16.h>
#include <math_constants.h>
#include <cstdint>

#define BB 32
#define CC 9
#define TT 4096
#define NC 512
#define CD 64
#define KTOT 192          // hi | lo | hi split-K
#define MBLK 128          // positions per block
#define KP_B 400          // padded SMEM row stride in bytes (200 bf16)
#define CROWS 64          // codes per chunk (8 chunks)
#define NROWS (BB * CC)   // 288 real rows
#define NPAIR (NROWS / 2) // 144 packed FFTs

#define OFF_IDX ((size_t)BB * TT * CD)
#define OFF_PH  (OFF_IDX + (size_t)BB * TT)

// SMEM map for quant kernel (bytes)
#define SM_A    0u
#define SM_B0   51200u
#define SM_B1   76800u
#define SM_CN   102400u
#define SM_RBV  104448u   // float [128][2] per-nwarp best
#define SM_RBI  105472u   // int   [128][2] per-nwarp idx
#define SM_IDX  106496u   // int   [128]
#define SMEMSZ  107008    // 2 CTAs/SM

// ---------------- global scratch ----------------
__device__ float g_phase[BB * CC * TT];
__device__ __align__(16) __nv_bfloat16 g_B[NC * KTOT];   // segs (hi,hi,lo)
__device__ float g_cn[NC];

__device__ __forceinline__ uint32_t smem_to_u32(const void* p) {
    uint32_t a;
    asm("{ .reg .u64 t; cvta.to.shared.u64 t, %1; cvt.u32.u64 %0, t; }"
        : "=r"(a) : "l"(p));
    return a;
}

#define LDSM_X4(r0, r1, r2, r3, addr) \
    asm volatile("ldmatrix.sync.aligned.m8n8.x4.shared.b16 {%0,%1,%2,%3}, [%4];" \
                 : "=r"(r0), "=r"(r1), "=r"(r2), "=r"(r3) : "r"(addr))

#define MMA16816(d, a, b0, b1) \
    asm volatile("mma.sync.aligned.m16n8k16.row.col.f32.bf16.bf16.f32 " \
                 "{%0,%1,%2,%3}, {%4,%5,%6,%7}, {%8,%9}, {%0,%1,%2,%3};" \
                 : "+f"((d)[0]), "+f"((d)[1]), "+f"((d)[2]), "+f"((d)[3]) \
                 : "r"((a)[0]), "r"((a)[1]), "r"((a)[2]), "r"((a)[3]), \
                   "r"(b0), "r"(b1))

#define CP_ASYNC16(saddr, gptr) \
    asm volatile("cp.async.cg.shared.global [%0], [%1], 16;" \
                 :: "r"(saddr), "l"(gptr) : "memory")
#define CP_COMMIT() asm volatile("cp.async.commit_group;" ::: "memory")
#define CP_WAIT(n)  asm volatile("cp.async.wait_group %0;" :: "n"(n) : "memory")

__device__ __forceinline__ float2 cmulf(float2 a, float2 b) {
    return make_float2(a.x * b.x - a.y * b.y, a.x * b.y + a.y * b.x);
}
__device__ __forceinline__ float2 f2add(float2 a, float2 b) {
    return make_float2(a.x + b.x, a.y + b.y);
}
__device__ __forceinline__ float2 f2sub(float2 a, float2 b) {
    return make_float2(a.x - b.x, a.y - b.y);
}

__device__ __forceinline__ void split_pack(float v0, float v1,
                                           uint32_t& hp, uint32_t& lp) {
    __nv_bfloat16 h0 = __float2bfloat16(v0), h1 = __float2bfloat16(v1);
    __nv_bfloat16 l0 = __float2bfloat16(v0 - __bfloat162float(h0));
    __nv_bfloat16 l1 = __float2bfloat16(v1 - __bfloat162float(h1));
    hp = ((uint32_t)__bfloat16_as_ushort(h1) << 16) | __bfloat16_as_ushort(h0);
    lp = ((uint32_t)__bfloat16_as_ushort(l1) << 16) | __bfloat16_as_ushort(l0);
}

// ---------------- kernel 1: packed Hilbert FFT + fused codebook convert ----
// blocks [0, 144): two real rows packed as one complex FFT (512 thr).
// blocks [144, 176): codebook convert (16 warps each).
__global__ void fft_conv_kernel(const float* __restrict__ imu,
                                const float* __restrict__ cb) {
    const int tid = threadIdx.x;

    if (blockIdx.x >= NPAIR) {
        // ---- codebook convert: warp per code (16 warps) ----
        const int wid = tid >> 5, lane = tid & 31;
        const int c = (blockIdx.x - NPAIR) * 16 + wid;
        const float2 v = ((const float2*)(cb + (size_t)c * CD))[lane];
        float n = v.x * v.x + v.y * v.y;
        uint32_t hp, lp;
        split_pack(v.x, v.y, hp, lp);
        uint32_t* row32 = (uint32_t*)(g_B + (size_t)c * KTOT);
        row32[lane] = hp;
        row32[32 + lane] = hp;
        row32[64 + lane] = lp;
#pragma unroll
        for (int off = 16; off >= 1; off >>= 1)
            n += __shfl_xor_sync(0xffffffffu, n, off);
        if (lane == 0) g_cn[c] = n;
        return;
    }

    extern __shared__ float2 dsh[];
    float2* s = dsh;            // 4096
    float2* tw = dsh + TT;      // 4096: tw[k] = exp(-2*pi*i*k/4096)
    const float* x0 = imu + (size_t)(2 * blockIdx.x) * TT;
    const float* x1 = x0 + TT;

    for (int k = tid; k < TT; k += 512) {
        float sn, cs;
        sincosf(-(float)CUDART_PI_F * (float)k / 2048.0f, &sn, &cs);
        tw[k] = make_float2(cs, sn);
    }
    // pack two real rows into one complex signal
    for (int t = tid; t < TT; t += 512)
        s[t] = make_float2(x0[t], x1[t]);
    __syncthreads();

    // Forward radix-4 DIF: natural in, base-4 digit-reversed out.
#pragma unroll
    for (int ls = 10; ls >= 0; ls -= 2) {
        const int L = 1 << ls;
        const int m = 1024 >> ls;
        for (int i = tid; i < 1024; i += 512) {
            const int j = i & (L - 1);
            const int i0 = ((i >> ls) << (ls + 2)) + j;
            float2 a = s[i0], b = s[i0 + L], c = s[i0 + 2 * L], d = s[i0 + 3 * L];
            float2 t0 = f2add(a, c), t1 = f2sub(a, c);
            float2 t2 = f2add(b, d), t3 = f2sub(b, d);
            s[i0] = f2add(t0, t2);
            s[i0 + L] = cmulf(make_float2(t1.x + t3.y, t1.y - t3.x), tw[j * m]);
            s[i0 + 2 * L] = cmulf(f2sub(t0, t2), tw[2 * j * m]);
            s[i0 + 3 * L] = cmulf(make_float2(t1.x - t3.y, t1.y + t3.x), tw[3 * j * m]);
        }
        __syncthreads();
    }

    // Hilbert multiplier M[k] = -i*sgn(k) applied at base-4 digit-reversed slot.
    for (int p = tid; p < TT; p += 512) {
        const int r = (int)(__brev((unsigned)p) >> 20);         // 12-bit reverse
        const int k = ((r & 0x555) << 1) | ((r >> 1) & 0x555);  // swap bit pairs
        float2 v = s[p];
        if (k == 0 || k == TT / 2)  s[p] = make_float2(0.0f, 0.0f);
        else if (k < TT / 2)        s[p] = make_float2(v.y, -v.x);
        else                        s[p] = make_float2(-v.y, v.x);
    }
    __syncthreads();

    // Inverse radix-4 DIT: digit-reversed in, natural out (conj twiddles, no 1/N).
#pragma unroll
    for (int ls = 0; ls <= 10; ls += 2) {
        const int L = 1 << ls;
        const int m = 1024 >> ls;
        for (int i = tid; i < 1024; i += 512) {
            const int j = i & (L - 1);
            const int i0 = ((i >> ls) << (ls + 2)) + j;
            float2 w1 = tw[j * m], w2 = tw[2 * j * m], w3 = tw[3 * j * m];
            float2 A = s[i0];
            float2 Bv = cmulf(s[i0 + L],     make_float2(w1.x, -w1.y));
            float2 Cv = cmulf(s[i0 + 2 * L], make_float2(w2.x, -w2.y));
            float2 Dv = cmulf(s[i0 + 3 * L], make_float2(w3.x, -w3.y));
            float2 t0 = f2add(A, Cv), t1 = f2sub(A, Cv);
            float2 t2 = f2add(Bv, Dv), t3 = f2sub(Bv, Dv);
            s[i0] = f2add(t0, t2);
            s[i0 + L] = make_float2(t1.x - t3.y, t1.y + t3.x);
            s[i0 + 2 * L] = f2sub(t0, t2);
            s[i0 + 3 * L] = make_float2(t1.x + t3.y, t1.y - t3.x);
        }
        __syncthreads();
    }

    // phases: Re(analytic) = x exactly; Im = s/N (scale both by N instead)
    float* ph0 = g_phase + (size_t)(2 * blockIdx.x) * TT;
    float* ph1 = ph0 + TT;
    for (int t = tid; t < TT; t += 512) {
        const float2 v = s[t];
        ph0[t] = atan2f(v.x, 4096.0f * x0[t]);
        ph1[t] = atan2f(v.y, 4096.0f * x1[t]);
    }
}

// ---------------- kernel 2: fused features + HMMA GEMM + argmin ----------
__device__ __forceinline__ void prefetch_chunk(uint32_t sdst, int ch, int tid) {
    const char* src = (const char*)g_B + (size_t)ch * CROWS * KTOT * 2;
#pragma unroll
    for (int it = 0; it < 6; ++it) {
        const int i = tid + it * 256;       // 1536 uint4 total
        const int r = i / 24, kq = i - r * 24;
        CP_ASYNC16(sdst + (uint32_t)r * KP_B + (uint32_t)kq * 16u,
                   src + (size_t)r * 384 + (size_t)kq * 16);
    }
    CP_COMMIT();
}

__global__ void __launch_bounds__(256, 2)
quant_kernel(const float* __restrict__ imu,
             const float* __restrict__ Wm,
             const float* __restrict__ bm,
             const float* __restrict__ Wp,
             const float* __restrict__ bp,
             const float* __restrict__ cb,
             float* __restrict__ out) {
    extern __shared__ char smem[];
    const uint32_t sbase = smem_to_u32(smem);
    const int tid = threadIdx.x;
    const int wid = tid >> 5;
    const int lane = tid & 31;
    const int pbase = blockIdx.x * MBLK;

    float* scn = (float*)(smem + SM_CN);
    float* rbv = (float*)(smem + SM_RBV);
    int* rbi = (int*)(smem + SM_RBI);
    int* sidx = (int*)(smem + SM_IDX);

    // start B pipeline before the heavy feature phase
    prefetch_chunk(sbase + SM_B0, 0, tid);
    prefetch_chunk(sbase + SM_B1, 1, tid);

    for (int i = tid; i < NC; i += 256) scn[i] = g_cn[i];

    // ---- features for 128 positions -> SMEM A (bf16 split)
    if (tid < MBLK) {
        const int p = pbase + tid;
        const int b = p >> 12;
        const int t = p & (TT - 1);

        const float* xb = imu + (size_t)b * CC * TT + t;
        float xc[9];
#pragma unroll
        for (int c = 0; c < 9; ++c) xc[c] = xb[c * TT];

        const float* phb = g_phase + (size_t)b * CC * TT + t;
        float pm = 0.0f;
#pragma unroll
        for (int c = 0; c < 9; ++c) pm += phb[c * TT];
        pm *= (1.0f / 9.0f);
        float sp, cp;
        sincosf(pm, &sp, &cp);
        out[OFF_PH + p] = pm;

        float f[64];
#pragma unroll
        for (int i = 0; i < 32; ++i) {
            float a = bm[i];
#pragma unroll
            for (int c = 0; c < 9; ++c) a += Wm[i * 9 + c] * xc[c];
            f[i] = a;
        }
        float comb[9];
#pragma unroll
        for (int c = 0; c < 7; ++c) comb[c] = xc[c];
        comb[7] = cp;
        comb[8] = sp;
#pragma unroll
        for (int i = 0; i < 32; ++i) {
            float a = bp[i];
#pragma unroll
            for (int c = 0; c < 9; ++c) a += Wp[i * 9 + c] * comb[c];
            f[32 + i] = a;
        }

        uint32_t* row32 = (uint32_t*)(smem + SM_A + (uint32_t)tid * KP_B);
#pragma unroll
        for (int q = 0; q < 32; ++q) {
            uint32_t hp, lp;
            split_pack(f[2 * q], f[2 * q + 1], hp, lp);
            row32[q] = hp;            // seg0: f_hi
            row32[32 + q] = lp;       // seg1: f_lo
            row32[64 + q] = hp;       // seg2: f_hi
        }
    }
    __syncthreads();   // A + cn visible

    // ---- GEMM + argmin. Warp tile m32 x n32: 4 m-warps x 2 n-warps.
    const int wrow = wid & 3;
    const int wcol = wid >> 2;
    const int m0 = wrow * 32;

    float best[4];
    int bidx[4];
#pragma unroll
    for (int i = 0; i < 4; ++i) { best[i] = CUDART_INF_F; bidx[i] = 0; }

    const int mgrp = lane >> 3;     // 0..3
    const int mrow = lane & 7;
    const uint32_t a_base = sbase + SM_A
        + (uint32_t)(m0 + mrow + 8 * (mgrp & 1)) * KP_B
        + (uint32_t)(8 * (mgrp >> 1)) * 2u;
    const uint32_t b_base = (uint32_t)(wcol * 32) * KP_B
        + (uint32_t)(8 * (mgrp >> 1) + mrow) * KP_B
        + (uint32_t)(8 * (mgrp & 1)) * 2u;

#pragma unroll 1
    for (int ch = 0; ch < 8; ++ch) {
        if (ch < 7) { CP_WAIT(1); } else { CP_WAIT(0); }
        __syncthreads();            // chunk buffer complete for all warps

        const uint32_t sB = sbase + ((ch & 1) ? SM_B1 : SM_B0);

        float acc[2][4][4];
#pragma unroll
        for (int mt = 0; mt < 2; ++mt)
#pragma unroll
            for (int j = 0; j < 4; ++j)
#pragma unroll
                for (int q = 0; q < 4; ++q) acc[mt][j][q] = 0.0f;

#pragma unroll
        for (int ks = 0; ks < 12; ++ks) {
            const uint32_t koff = (uint32_t)ks * 32u;
            uint32_t a0[4], a1[4], b0q[4], b1q[4];
            LDSM_X4(a0[0], a0[1], a0[2], a0[3], a_base + koff);
            LDSM_X4(a1[0], a1[1], a1[2], a1[3], a_base + 16u * KP_B + koff);
            LDSM_X4(b0q[0], b0q[1], b0q[2], b0q[3], sB + b_base + koff);
            LDSM_X4(b1q[0], b1q[1], b1q[2], b1q[3], sB + b_base + 16u * KP_B + koff);
            MMA16816(acc[0][0], a0, b0q[0], b0q[1]);
            MMA16816(acc[0][1], a0, b0q[2], b0q[3]);
            MMA16816(acc[0][2], a0, b1q[0], b1q[1]);
            MMA16816(acc[0][3], a0, b1q[2], b1q[3]);
            MMA16816(acc[1][0], a1, b0q[0], b0q[1]);
            MMA16816(acc[1][1], a1, b0q[2], b0q[3]);
            MMA16816(acc[1][2], a1, b1q[0], b1q[1]);
            MMA16816(acc[1][3], a1, b1q[2], b1q[3]);
        }

        // running argmin (codes strictly increasing -> first-min kept)
#pragma unroll
        for (int mt = 0; mt < 2; ++mt)
#pragma unroll
            for (int j = 0; j < 4; ++j) {
                const int c0 = ch * CROWS + wcol * 32 + (j >> 1) * 16
                               + (j & 1) * 8 + (lane & 3) * 2;
                const float n0v = scn[c0], n1v = scn[c0 + 1];
                const float d0 = fmaf(-2.0f, acc[mt][j][0], n0v);
                const float d1 = fmaf(-2.0f, acc[mt][j][1], n1v);
                const float d2 = fmaf(-2.0f, acc[mt][j][2], n0v);
                const float d3 = fmaf(-2.0f, acc[mt][j][3], n1v);
                const int s0 = 2 * mt, s1 = 2 * mt + 1;
                if (d0 < best[s0]) { best[s0] = d0; bidx[s0] = c0; }
                if (d1 < best[s0]) { best[s0] = d1; bidx[s0] = c0 + 1; }
                if (d2 < best[s1]) { best[s1] = d2; bidx[s1] = c0; }
                if (d3 < best[s1]) { best[s1] = d3; bidx[s1] = c0 + 1; }
            }

        __syncthreads();            // all warps done reading this buffer
        if (ch < 6) prefetch_chunk(sbase + ((ch & 1) ? SM_B1 : SM_B0),
                                   ch + 2, tid);
    }

    // reduce across the 4 lanes sharing each row (quad)
#pragma unroll
    for (int off = 1; off <= 2; off <<= 1) {
#pragma unroll
        for (int s = 0; s < 4; ++s) {
            float ob = __shfl_xor_sync(0xffffffffu, best[s], off);
            int oi = __shfl_xor_sync(0xffffffffu, bidx[s], off);
            if (ob < best[s] || (ob == best[s] && oi < bidx[s])) {
                best[s] = ob; bidx[s] = oi;
            }
        }
    }
    if ((lane & 3) == 0) {
        const int r = lane >> 2;
#pragma unroll
        for (int mt = 0; mt < 2; ++mt)
#pragma unroll
            for (int h = 0; h < 2; ++h) {
                const int row = m0 + mt * 16 + 8 * h + r;
                rbv[row * 2 + wcol] = best[2 * mt + h];
                rbi[row * 2 + wcol] = bidx[2 * mt + h];
            }
    }
    __syncthreads();

    // cross-nwarp reduce: one thread per row
    if (tid < MBLK) {
        float bv = rbv[tid * 2];
        int bi = rbi[tid * 2];
        const float ov = rbv[tid * 2 + 1];
        const int oi = rbi[tid * 2 + 1];
        if (ov < bv || (ov == bv && oi < bi)) { bv = ov; bi = oi; }
        sidx[tid] = bi;
        out[OFF_IDX + pbase + tid] = (float)bi;
    }
    __syncthreads();

    // quantized rows from fp32 codebook (L2-hot)
    const float4* cb4 = (const float4*)cb;
    for (int q = tid; q < MBLK * (CD / 4); q += 256) {
        const int pos = q >> 4;
        const int w = q & 15;
        ((float4*)(out + (size_t)(pbase + pos) * CD))[w] =
            cb4[(size_t)sidx[pos] * (CD / 4) + w];
    }
}

// ---------------- launch ----------------
extern "C" void kernel_launch(void* const* d_in, const int* in_sizes, int n_in,
                              void* d_out, int out_size) {
    const float* imu = (const float*)d_in[0];
    const float* Wm  = (const float*)d_in[1];
    const float* bm  = (const float*)d_in[2];
    const float* Wp  = (const float*)d_in[3];
    const float* bp  = (const float*)d_in[4];
    const float* cb  = (const float*)d_in[5];
    float* out = (float*)d_out;

    const int fft_smem = 2 * TT * (int)sizeof(float2);  // 64 KB
    cudaFuncSetAttribute(fft_conv_kernel,
                         cudaFuncAttributeMaxDynamicSharedMemorySize, fft_smem);
    fft_conv_kernel<<<NPAIR + NC / 16, 512, fft_smem>>>(imu, cb);

    cudaFuncSetAttribute(quant_kernel,
                         cudaFuncAttributeMaxDynamicSharedMemorySize, SMEMSZ);
    quant_kernel<<<(BB * TT) / MBLK, 256, SMEMSZ>>>(imu, Wm, bm, Wp, bp, cb, out);
}

// round 11
// speedup vs baseline: 1.5300x; 1.0858x over previous
#include <cuda_runtime.h>
#include <cuda_bf16.h>
#include <math_constants.h>
#include <cstdint>

#define BB 32
#define CC 9
#define TT 4096
#define NC 512
#define CD 64
#define MBLK 128          // positions per block
#define KP_B 272          // padded SMEM row stride bytes (128B hi + 128B lo + 16 pad)
#define CROWS 64          // codes per chunk (8 chunks)
#define NROWS (BB * CC)   // 288 real rows
#define NPAIR (NROWS / 2) // 144 packed FFTs

#define OFF_IDX ((size_t)BB * TT * CD)
#define OFF_PH  (OFF_IDX + (size_t)BB * TT)

// SMEM map for quant kernel (bytes)
#define SM_A    0u        // 128 * 272 = 34816
#define SM_B0   34816u    // 64 * 272 = 17408
#define SM_B1   52224u
#define SM_CN   69632u    // 2048
#define SM_RBV  71680u    // float [128][2]
#define SM_RBI  72704u    // int   [128][2]
#define SM_IDX  73728u    // int   [128]
#define SMEMSZ  74240     // 2 CTAs/SM

// ---------------- global scratch ----------------
__device__ float g_phase[BB * CC * TT];
__device__ __align__(16) __nv_bfloat16 g_B[NC * 128];    // per code: hi[64] | lo[64]
__device__ float g_cn[NC];

__device__ __forceinline__ uint32_t smem_to_u32(const void* p) {
    uint32_t a;
    asm("{ .reg .u64 t; cvta.to.shared.u64 t, %1; cvt.u32.u64 %0, t; }"
        : "=r"(a) : "l"(p));
    return a;
}

#define LDSM_X4(r0, r1, r2, r3, addr) \
    asm volatile("ldmatrix.sync.aligned.m8n8.x4.shared.b16 {%0,%1,%2,%3}, [%4];" \
                 : "=r"(r0), "=r"(r1), "=r"(r2), "=r"(r3) : "r"(addr))

#define MMA16816(d, a, b0, b1) \
    asm volatile("mma.sync.aligned.m16n8k16.row.col.f32.bf16.bf16.f32 " \
                 "{%0,%1,%2,%3}, {%4,%5,%6,%7}, {%8,%9}, {%0,%1,%2,%3};" \
                 : "+f"((d)[0]), "+f"((d)[1]), "+f"((d)[2]), "+f"((d)[3]) \
                 : "r"((a)[0]), "r"((a)[1]), "r"((a)[2]), "r"((a)[3]), \
                   "r"(b0), "r"(b1))

#define CP_ASYNC16(saddr, gptr) \
    asm volatile("cp.async.cg.shared.global [%0], [%1], 16;" \
                 :: "r"(saddr), "l"(gptr) : "memory")
#define CP_COMMIT() asm volatile("cp.async.commit_group;" ::: "memory")
#define CP_WAIT(n)  asm volatile("cp.async.wait_group %0;" :: "n"(n) : "memory")

__device__ __forceinline__ float2 cmulf(float2 a, float2 b) {
    return make_float2(a.x * b.x - a.y * b.y, a.x * b.y + a.y * b.x);
}
__device__ __forceinline__ float2 f2add(float2 a, float2 b) {
    return make_float2(a.x + b.x, a.y + b.y);
}
__device__ __forceinline__ float2 f2sub(float2 a, float2 b) {
    return make_float2(a.x - b.x, a.y - b.y);
}

__device__ __forceinline__ void split_pack(float v0, float v1,
                                           uint32_t& hp, uint32_t& lp) {
    __nv_bfloat16 h0 = __float2bfloat16(v0), h1 = __float2bfloat16(v1);
    __nv_bfloat16 l0 = __float2bfloat16(v0 - __bfloat162float(h0));
    __nv_bfloat16 l1 = __float2bfloat16(v1 - __bfloat162float(h1));
    hp = ((uint32_t)__bfloat16_as_ushort(h1) << 16) | __bfloat16_as_ushort(h0);
    lp = ((uint32_t)__bfloat16_as_ushort(l1) << 16) | __bfloat16_as_ushort(l0);
}

// ---------------- kernel 1: packed Hilbert FFT + fused codebook convert ----
__global__ void fft_conv_kernel(const float* __restrict__ imu,
                                const float* __restrict__ cb) {
    const int tid = threadIdx.x;

    if (blockIdx.x >= NPAIR) {
        // ---- codebook convert: warp per code (16 warps) ----
        const int wid = tid >> 5, lane = tid & 31;
        const int c = (blockIdx.x - NPAIR) * 16 + wid;
        const float2 v = ((const float2*)(cb + (size_t)c * CD))[lane];
        float n = v.x * v.x + v.y * v.y;
        uint32_t hp, lp;
        split_pack(v.x, v.y, hp, lp);
        uint32_t* row32 = (uint32_t*)(g_B + (size_t)c * 128);
        row32[lane] = hp;
        row32[32 + lane] = lp;
#pragma unroll
        for (int off = 16; off >= 1; off >>= 1)
            n += __shfl_xor_sync(0xffffffffu, n, off);
        if (lane == 0) g_cn[c] = n;
        return;
    }

    extern __shared__ float2 dsh[];
    float2* s = dsh;            // 4096
    float2* tw = dsh + TT;      // 4096: tw[k] = exp(-2*pi*i*k/4096)
    const float* x0 = imu + (size_t)(2 * blockIdx.x) * TT;
    const float* x1 = x0 + TT;

    for (int k = tid; k < TT; k += 512) {
        float sn, cs;
        sincosf(-(float)CUDART_PI_F * (float)k / 2048.0f, &sn, &cs);
        tw[k] = make_float2(cs, sn);
    }
    for (int t = tid; t < TT; t += 512)
        s[t] = make_float2(x0[t], x1[t]);
    __syncthreads();

    // Forward radix-4 DIF: natural in, base-4 digit-reversed out.
#pragma unroll
    for (int ls = 10; ls >= 0; ls -= 2) {
        const int L = 1 << ls;
        const int m = 1024 >> ls;
        for (int i = tid; i < 1024; i += 512) {
            const int j = i & (L - 1);
            const int i0 = ((i >> ls) << (ls + 2)) + j;
            float2 a = s[i0], b = s[i0 + L], c = s[i0 + 2 * L], d = s[i0 + 3 * L];
            float2 t0 = f2add(a, c), t1 = f2sub(a, c);
            float2 t2 = f2add(b, d), t3 = f2sub(b, d);
            s[i0] = f2add(t0, t2);
            s[i0 + L] = cmulf(make_float2(t1.x + t3.y, t1.y - t3.x), tw[j * m]);
            s[i0 + 2 * L] = cmulf(f2sub(t0, t2), tw[2 * j * m]);
            s[i0 + 3 * L] = cmulf(make_float2(t1.x - t3.y, t1.y + t3.x), tw[3 * j * m]);
        }
        __syncthreads();
    }

    // Hilbert multiplier M[k] = -i*sgn(k) at base-4 digit-reversed slot.
    for (int p = tid; p < TT; p += 512) {
        const int r = (int)(__brev((unsigned)p) >> 20);
        const int k = ((r & 0x555) << 1) | ((r >> 1) & 0x555);
        float2 v = s[p];
        if (k == 0 || k == TT / 2)  s[p] = make_float2(0.0f, 0.0f);
        else if (k < TT / 2)        s[p] = make_float2(v.y, -v.x);
        else                        s[p] = make_float2(-v.y, v.x);
    }
    __syncthreads();

    // Inverse radix-4 DIT: digit-reversed in, natural out (conj twiddles, no 1/N).
#pragma unroll
    for (int ls = 0; ls <= 10; ls += 2) {
        const int L = 1 << ls;
        const int m = 1024 >> ls;
        for (int i = tid; i < 1024; i += 512) {
            const int j = i & (L - 1);
            const int i0 = ((i >> ls) << (ls + 2)) + j;
            float2 w1 = tw[j * m], w2 = tw[2 * j * m], w3 = tw[3 * j * m];
            float2 A = s[i0];
            float2 Bv = cmulf(s[i0 + L],     make_float2(w1.x, -w1.y));
            float2 Cv = cmulf(s[i0 + 2 * L], make_float2(w2.x, -w2.y));
            float2 Dv = cmulf(s[i0 + 3 * L], make_float2(w3.x, -w3.y));
            float2 t0 = f2add(A, Cv), t1 = f2sub(A, Cv);
            float2 t2 = f2add(Bv, Dv), t3 = f2sub(Bv, Dv);
            s[i0] = f2add(t0, t2);
            s[i0 + L] = make_float2(t1.x - t3.y, t1.y + t3.x);
            s[i0 + 2 * L] = f2sub(t0, t2);
            s[i0 + 3 * L] = make_float2(t1.x + t3.y, t1.y - t3.x);
        }
        __syncthreads();
    }

    float* ph0 = g_phase + (size_t)(2 * blockIdx.x) * TT;
    float* ph1 = ph0 + TT;
    for (int t = tid; t < TT; t += 512) {
        const float2 v = s[t];
        ph0[t] = atan2f(v.x, 4096.0f * x0[t]);
        ph1[t] = atan2f(v.y, 4096.0f * x1[t]);
    }
}

// ---------------- kernel 2: fused features + HMMA GEMM + argmin ----------
__device__ __forceinline__ void prefetch_chunk(uint32_t sdst, int ch, int tid) {
    const char* src = (const char*)g_B + (size_t)ch * CROWS * 256;
#pragma unroll
    for (int it = 0; it < 4; ++it) {
        const int i = tid + it * 256;       // 1024 uint4 total
        const int r = i >> 4, kq = i & 15;
        CP_ASYNC16(sdst + (uint32_t)r * KP_B + (uint32_t)kq * 16u,
                   src + (size_t)r * 256 + (size_t)kq * 16);
    }
    CP_COMMIT();
}

__global__ void __launch_bounds__(256, 2)
quant_kernel(const float* __restrict__ imu,
             const float* __restrict__ Wm,
             const float* __restrict__ bm,
             const float* __restrict__ Wp,
             const float* __restrict__ bp,
             const float* __restrict__ cb,
             float* __restrict__ out) {
    extern __shared__ char smem[];
    const uint32_t sbase = smem_to_u32(smem);
    const int tid = threadIdx.x;
    const int wid = tid >> 5;
    const int lane = tid & 31;
    const int pbase = blockIdx.x * MBLK;

    float* scn = (float*)(smem + SM_CN);
    float* rbv = (float*)(smem + SM_RBV);
    int* rbi = (int*)(smem + SM_RBI);
    int* sidx = (int*)(smem + SM_IDX);

    // start B pipeline before the heavy feature phase
    prefetch_chunk(sbase + SM_B0, 0, tid);
    prefetch_chunk(sbase + SM_B1, 1, tid);

    for (int i = tid; i < NC; i += 256) scn[i] = g_cn[i];

    // ---- features for 128 positions -> SMEM A (bf16 hi|lo)
    if (tid < MBLK) {
        const int p = pbase + tid;
        const int b = p >> 12;
        const int t = p & (TT - 1);

        const float* xb = imu + (size_t)b * CC * TT + t;
        float xc[9];
#pragma unroll
        for (int c = 0; c < 9; ++c) xc[c] = xb[c * TT];

        const float* phb = g_phase + (size_t)b * CC * TT + t;
        float pm = 0.0f;
#pragma unroll
        for (int c = 0; c < 9; ++c) pm += phb[c * TT];
        pm *= (1.0f / 9.0f);
        float sp, cp;
        sincosf(pm, &sp, &cp);
        out[OFF_PH + p] = pm;

        float f[64];
#pragma unroll
        for (int i = 0; i < 32; ++i) {
            float a = bm[i];
#pragma unroll
            for (int c = 0; c < 9; ++c) a += Wm[i * 9 + c] * xc[c];
            f[i] = a;
        }
        float comb[9];
#pragma unroll
        for (int c = 0; c < 7; ++c) comb[c] = xc[c];
        comb[7] = cp;
        comb[8] = sp;
#pragma unroll
        for (int i = 0; i < 32; ++i) {
            float a = bp[i];
#pragma unroll
            for (int c = 0; c < 9; ++c) a += Wp[i * 9 + c] * comb[c];
            f[32 + i] = a;
        }

        uint32_t* row32 = (uint32_t*)(smem + SM_A + (uint32_t)tid * KP_B);
#pragma unroll
        for (int q = 0; q < 32; ++q) {
            uint32_t hp, lp;
            split_pack(f[2 * q], f[2 * q + 1], hp, lp);
            row32[q] = hp;            // f_hi (bytes 0..127)
            row32[32 + q] = lp;       // f_lo (bytes 128..255)
        }
    }
    __syncthreads();   // A + cn visible

    // ---- GEMM + argmin. Warp tile m32 x n32: 4 m-warps x 2 n-warps.
    const int wrow = wid & 3;
    const int wcol = wid >> 2;
    const int m0 = wrow * 32;

    float best[4];
    int bidx[4];
#pragma unroll
    for (int i = 0; i < 4; ++i) { best[i] = CUDART_INF_F; bidx[i] = 0; }

    const int mgrp = lane >> 3;     // 0..3
    const int mrow = lane & 7;
    const uint32_t a_base = sbase + SM_A
        + (uint32_t)(m0 + mrow + 8 * (mgrp & 1)) * KP_B
        + (uint32_t)(8 * (mgrp >> 1)) * 2u;
    const uint32_t b_base = (uint32_t)(wcol * 32) * KP_B
        + (uint32_t)(8 * (mgrp >> 1) + mrow) * KP_B
        + (uint32_t)(8 * (mgrp & 1)) * 2u;

#pragma unroll 1
    for (int ch = 0; ch < 8; ++ch) {
        if (ch < 7) { CP_WAIT(1); } else { CP_WAIT(0); }
        __syncthreads();            // chunk buffer complete for all warps

        const uint32_t sB = sbase + ((ch & 1) ? SM_B1 : SM_B0);

        float acc[2][4][4];
#pragma unroll
        for (int mt = 0; mt < 2; ++mt)
#pragma unroll
            for (int j = 0; j < 4; ++j)
#pragma unroll
                for (int q = 0; q < 4; ++q) acc[mt][j][q] = 0.0f;

        // acc += A_hi*B_hi + A_lo*B_hi + A_hi*B_lo  (4 k-quads of 16)
#pragma unroll
        for (int kq = 0; kq < 4; ++kq) {
            const uint32_t koff = (uint32_t)kq * 32u;
            uint32_t ah0[4], ah1[4], al0[4], al1[4];
            uint32_t bh0[4], bh1[4], bl0[4], bl1[4];
            LDSM_X4(ah0[0], ah0[1], ah0[2], ah0[3], a_base + koff);
            LDSM_X4(ah1[0], ah1[1], ah1[2], ah1[3], a_base + 16u * KP_B + koff);
            LDSM_X4(al0[0], al0[1], al0[2], al0[3], a_base + 128u + koff);
            LDSM_X4(al1[0], al1[1], al1[2], al1[3], a_base + 16u * KP_B + 128u + koff);
            LDSM_X4(bh0[0], bh0[1], bh0[2], bh0[3], sB + b_base + koff);
            LDSM_X4(bh1[0], bh1[1], bh1[2], bh1[3], sB + b_base + 16u * KP_B + koff);
            LDSM_X4(bl0[0], bl0[1], bl0[2], bl0[3], sB + b_base + 128u + koff);
            LDSM_X4(bl1[0], bl1[1], bl1[2], bl1[3], sB + b_base + 16u * KP_B + 128u + koff);
            // hi x hi
            MMA16816(acc[0][0], ah0, bh0[0], bh0[1]);
            MMA16816(acc[0][1], ah0, bh0[2], bh0[3]);
            MMA16816(acc[0][2], ah0, bh1[0], bh1[1]);
            MMA16816(acc[0][3], ah0, bh1[2], bh1[3]);
            MMA16816(acc[1][0], ah1, bh0[0], bh0[1]);
            MMA16816(acc[1][1], ah1, bh0[2], bh0[3]);
            MMA16816(acc[1][2], ah1, bh1[0], bh1[1]);
            MMA16816(acc[1][3], ah1, bh1[2], bh1[3]);
            // lo x hi
            MMA16816(acc[0][0], al0, bh0[0], bh0[1]);
            MMA16816(acc[0][1], al0, bh0[2], bh0[3]);
            MMA16816(acc[0][2], al0, bh1[0], bh1[1]);
            MMA16816(acc[0][3], al0, bh1[2], bh1[3]);
            MMA16816(acc[1][0], al1, bh0[0], bh0[1]);
            MMA16816(acc[1][1], al1, bh0[2], bh0[3]);
            MMA16816(acc[1][2], al1, bh1[0], bh1[1]);
            MMA16816(acc[1][3], al1, bh1[2], bh1[3]);
            // hi x lo
            MMA16816(acc[0][0], ah0, bl0[0], bl0[1]);
            MMA16816(acc[0][1], ah0, bl0[2], bl0[3]);
            MMA16816(acc[0][2], ah0, bl1[0], bl1[1]);
            MMA16816(acc[0][3], ah0, bl1[2], bl1[3]);
            MMA16816(acc[1][0], ah1, bl0[0], bl0[1]);
            MMA16816(acc[1][1], ah1, bl0[2], bl0[3]);
            MMA16816(acc[1][2], ah1, bl1[0], bl1[1]);
            MMA16816(acc[1][3], ah1, bl1[2], bl1[3]);
        }

        // running argmin (codes strictly increasing -> first-min kept)
#pragma unroll
        for (int mt = 0; mt < 2; ++mt)
#pragma unroll
            for (int j = 0; j < 4; ++j) {
                const int c0 = ch * CROWS + wcol * 32 + (j >> 1) * 16
                               + (j & 1) * 8 + (lane & 3) * 2;
                const float n0v = scn[c0], n1v = scn[c0 + 1];
                const float d0 = fmaf(-2.0f, acc[mt][j][0], n0v);
                const float d1 = fmaf(-2.0f, acc[mt][j][1], n1v);
                const float d2 = fmaf(-2.0f, acc[mt][j][2], n0v);
                const float d3 = fmaf(-2.0f, acc[mt][j][3], n1v);
                const int s0 = 2 * mt, s1 = 2 * mt + 1;
                if (d0 < best[s0]) { best[s0] = d0; bidx[s0] = c0; }
                if (d1 < best[s0]) { best[s0] = d1; bidx[s0] = c0 + 1; }
                if (d2 < best[s1]) { best[s1] = d2; bidx[s1] = c0; }
                if (d3 < best[s1]) { best[s1] = d3; bidx[s1] = c0 + 1; }
            }

        __syncthreads();            // all warps done reading this buffer
        if (ch < 6) prefetch_chunk(sbase + ((ch & 1) ? SM_B1 : SM_B0),
                                   ch + 2, tid);
    }

    // reduce across the 4 lanes sharing each row (quad)
#pragma unroll
    for (int off = 1; off <= 2; off <<= 1) {
#pragma unroll
        for (int s = 0; s < 4; ++s) {
            float ob = __shfl_xor_sync(0xffffffffu, best[s], off);
            int oi = __shfl_xor_sync(0xffffffffu, bidx[s], off);
            if (ob < best[s] || (ob == best[s] && oi < bidx[s])) {
                best[s] = ob; bidx[s] = oi;
            }
        }
    }
    if ((lane & 3) == 0) {
        const int r = lane >> 2;
#pragma unroll
        for (int mt = 0; mt < 2; ++mt)
#pragma unroll
            for (int h = 0; h < 2; ++h) {
                const int row = m0 + mt * 16 + 8 * h + r;
                rbv[row * 2 + wcol] = best[2 * mt + h];
                rbi[row * 2 + wcol] = bidx[2 * mt + h];
            }
    }
    __syncthreads();

    // cross-nwarp reduce: one thread per row
    if (tid < MBLK) {
        float bv = rbv[tid * 2];
        int bi = rbi[tid * 2];
        const float ov = rbv[tid * 2 + 1];
        const int oi = rbi[tid * 2 + 1];
        if (ov < bv || (ov == bv && oi < bi)) { bv = ov; bi = oi; }
        sidx[tid] = bi;
        out[OFF_IDX + pbase + tid] = (float)bi;
    }
    __syncthreads();

    // quantized rows from fp32 codebook (L2-hot)
    const float4* cb4 = (const float4*)cb;
    for (int q = tid; q < MBLK * (CD / 4); q += 256) {
        const int pos = q >> 4;
        const int w = q & 15;
        ((float4*)(out + (size_t)(pbase + pos) * CD))[w] =
            cb4[(size_t)sidx[pos] * (CD / 4) + w];
    }
}

// ---------------- launch ----------------
extern "C" void kernel_launch(void* const* d_in, const int* in_sizes, int n_in,
                              void* d_out, int out_size) {
    const float* imu = (const float*)d_in[0];
    const float* Wm  = (const float*)d_in[1];
    const float* bm  = (const float*)d_in[2];
    const float* Wp  = (const float*)d_in[3];
    const float* bp  = (const float*)d_in[4];
    const float* cb  = (const float*)d_in[5];
    float* out = (float*)d_out;

    const int fft_smem = 2 * TT * (int)sizeof(float2);  // 64 KB
    cudaFuncSetAttribute(fft_conv_kernel,
                         cudaFuncAttributeMaxDynamicSharedMemorySize, fft_smem);
    fft_conv_kernel<<<NPAIR + NC / 16, 512, fft_smem>>>(imu, cb);

    cudaFuncSetAttribute(quant_kernel,
                         cudaFuncAttributeMaxDynamicSharedMemorySize, SMEMSZ);
    quant_kernel<<<(BB * TT) / MBLK, 256, SMEMSZ>>>(imu, Wm, bm, Wp, bp, cb, out);
}

// round 12
// speedup vs baseline: 1.5495x; 1.0127x over previous
#include <cuda_runtime.h>
#include <cuda_bf16.h>
#include <math_constants.h>
#include <cstdint>

#define BB 32
#define CC 9
#define TT 4096
#define NC 512
#define CD 64
#define MBLK 128          // positions per block
#define KP_B 272          // padded SMEM row stride bytes (128B hi + 128B lo + 16 pad)
#define CROWS 64          // codes per chunk (8 chunks)
#define NROWS (BB * CC)   // 288 real rows
#define NPAIR (NROWS / 2) // 144 packed FFTs

#define OFF_IDX ((size_t)BB * TT * CD)
#define OFF_PH  (OFF_IDX + (size_t)BB * TT)

// SMEM map for quant kernel (bytes)
#define SM_A    0u        // 128 * 272 = 34816
#define SM_B0   34816u    // 3 buffers x 64 * 272 = 17408 each
#define SM_CN   87040u    // 2048
#define SM_RBV  89088u    // float [128][2]
#define SM_RBI  90112u    // int   [128][2]
#define SM_IDX  91136u    // int   [128]
#define SMEMSZ  91648     // 2 CTAs/SM

// ---------------- global scratch ----------------
__device__ float g_phase[BB * CC * TT];
__device__ __align__(16) __nv_bfloat16 g_B[NC * 128];    // per code: hi[64] | lo[64]
__device__ float g_cn[NC];

__device__ __forceinline__ uint32_t smem_to_u32(const void* p) {
    uint32_t a;
    asm("{ .reg .u64 t; cvta.to.shared.u64 t, %1; cvt.u32.u64 %0, t; }"
        : "=r"(a) : "l"(p));
    return a;
}

#define LDSM_X4(r0, r1, r2, r3, addr) \
    asm volatile("ldmatrix.sync.aligned.m8n8.x4.shared.b16 {%0,%1,%2,%3}, [%4];" \
                 : "=r"(r0), "=r"(r1), "=r"(r2), "=r"(r3) : "r"(addr))

#define MMA16816(d, a, b0, b1) \
    asm volatile("mma.sync.aligned.m16n8k16.row.col.f32.bf16.bf16.f32 " \
                 "{%0,%1,%2,%3}, {%4,%5,%6,%7}, {%8,%9}, {%0,%1,%2,%3};" \
                 : "+f"((d)[0]), "+f"((d)[1]), "+f"((d)[2]), "+f"((d)[3]) \
                 : "r"((a)[0]), "r"((a)[1]), "r"((a)[2]), "r"((a)[3]), \
                   "r"(b0), "r"(b1))

#define CP_ASYNC16(saddr, gptr) \
    asm volatile("cp.async.cg.shared.global [%0], [%1], 16;" \
                 :: "r"(saddr), "l"(gptr) : "memory")
#define CP_COMMIT() asm volatile("cp.async.commit_group;" ::: "memory")
#define CP_WAIT(n)  asm volatile("cp.async.wait_group %0;" :: "n"(n) : "memory")

__device__ __forceinline__ float2 cmulf(float2 a, float2 b) {
    return make_float2(a.x * b.x - a.y * b.y, a.x * b.y + a.y * b.x);
}
__device__ __forceinline__ float2 f2add(float2 a, float2 b) {
    return make_float2(a.x + b.x, a.y + b.y);
}
__device__ __forceinline__ float2 f2sub(float2 a, float2 b) {
    return make_float2(a.x - b.x, a.y - b.y);
}

__device__ __forceinline__ void split_pack(float v0, float v1,
                                           uint32_t& hp, uint32_t& lp) {
    __nv_bfloat16 h0 = __float2bfloat16(v0), h1 = __float2bfloat16(v1);
    __nv_bfloat16 l0 = __float2bfloat16(v0 - __bfloat162float(h0));
    __nv_bfloat16 l1 = __float2bfloat16(v1 - __bfloat162float(h1));
    hp = ((uint32_t)__bfloat16_as_ushort(h1) << 16) | __bfloat16_as_ushort(h0);
    lp = ((uint32_t)__bfloat16_as_ushort(l1) << 16) | __bfloat16_as_ushort(l0);
}

// ---------------- kernel 1: packed Hilbert FFT + fused codebook convert ----
__global__ void fft_conv_kernel(const float* __restrict__ imu,
                                const float* __restrict__ cb) {
    const int tid = threadIdx.x;

    if (blockIdx.x >= NPAIR) {
        // ---- codebook convert: warp per code (16 warps) ----
        const int wid = tid >> 5, lane = tid & 31;
        const int c = (blockIdx.x - NPAIR) * 16 + wid;
        const float2 v = ((const float2*)(cb + (size_t)c * CD))[lane];
        float n = v.x * v.x + v.y * v.y;
        uint32_t hp, lp;
        split_pack(v.x, v.y, hp, lp);
        uint32_t* row32 = (uint32_t*)(g_B + (size_t)c * 128);
        row32[lane] = hp;
        row32[32 + lane] = lp;
#pragma unroll
        for (int off = 16; off >= 1; off >>= 1)
            n += __shfl_xor_sync(0xffffffffu, n, off);
        if (lane == 0) g_cn[c] = n;
        return;
    }

    extern __shared__ float2 dsh[];
    float2* s = dsh;            // 4096
    float2* tw = dsh + TT;      // 4096: tw[k] = exp(-2*pi*i*k/4096)
    const float* x0 = imu + (size_t)(2 * blockIdx.x) * TT;
    const float* x1 = x0 + TT;

    for (int k = tid; k < TT; k += 512) {
        float sn, cs;
        sincosf(-(float)CUDART_PI_F * (float)k / 2048.0f, &sn, &cs);
        tw[k] = make_float2(cs, sn);
    }
    for (int t = tid; t < TT; t += 512)
        s[t] = make_float2(x0[t], x1[t]);
    __syncthreads();

    // Forward radix-4 DIF: natural in, base-4 digit-reversed out.
#pragma unroll
    for (int ls = 10; ls >= 0; ls -= 2) {
        const int L = 1 << ls;
        const int m = 1024 >> ls;
        for (int i = tid; i < 1024; i += 512) {
            const int j = i & (L - 1);
            const int i0 = ((i >> ls) << (ls + 2)) + j;
            float2 a = s[i0], b = s[i0 + L], c = s[i0 + 2 * L], d = s[i0 + 3 * L];
            float2 t0 = f2add(a, c), t1 = f2sub(a, c);
            float2 t2 = f2add(b, d), t3 = f2sub(b, d);
            s[i0] = f2add(t0, t2);
            s[i0 + L] = cmulf(make_float2(t1.x + t3.y, t1.y - t3.x), tw[j * m]);
            s[i0 + 2 * L] = cmulf(f2sub(t0, t2), tw[2 * j * m]);
            s[i0 + 3 * L] = cmulf(make_float2(t1.x - t3.y, t1.y + t3.x), tw[3 * j * m]);
        }
        __syncthreads();
    }

    // Hilbert multiplier M[k] = -i*sgn(k) at base-4 digit-reversed slot.
    for (int p = tid; p < TT; p += 512) {
        const int r = (int)(__brev((unsigned)p) >> 20);
        const int k = ((r & 0x555) << 1) | ((r >> 1) & 0x555);
        float2 v = s[p];
        if (k == 0 || k == TT / 2)  s[p] = make_float2(0.0f, 0.0f);
        else if (k < TT / 2)        s[p] = make_float2(v.y, -v.x);
        else                        s[p] = make_float2(-v.y, v.x);
    }
    __syncthreads();

    // Inverse radix-4 DIT: digit-reversed in, natural out (conj twiddles, no 1/N).
#pragma unroll
    for (int ls = 0; ls <= 10; ls += 2) {
        const int L = 1 << ls;
        const int m = 1024 >> ls;
        for (int i = tid; i < 1024; i += 512) {
            const int j = i & (L - 1);
            const int i0 = ((i >> ls) << (ls + 2)) + j;
            float2 w1 = tw[j * m], w2 = tw[2 * j * m], w3 = tw[3 * j * m];
            float2 A = s[i0];
            float2 Bv = cmulf(s[i0 + L],     make_float2(w1.x, -w1.y));
            float2 Cv = cmulf(s[i0 + 2 * L], make_float2(w2.x, -w2.y));
            float2 Dv = cmulf(s[i0 + 3 * L], make_float2(w3.x, -w3.y));
            float2 t0 = f2add(A, Cv), t1 = f2sub(A, Cv);
            float2 t2 = f2add(Bv, Dv), t3 = f2sub(Bv, Dv);
            s[i0] = f2add(t0, t2);
            s[i0 + L] = make_float2(t1.x - t3.y, t1.y + t3.x);
            s[i0 + 2 * L] = f2sub(t0, t2);
            s[i0 + 3 * L] = make_float2(t1.x + t3.y, t1.y - t3.x);
        }
        __syncthreads();
    }

    float* ph0 = g_phase + (size_t)(2 * blockIdx.x) * TT;
    float* ph1 = ph0 + TT;
    for (int t = tid; t < TT; t += 512) {
        const float2 v = s[t];
        ph0[t] = atan2f(v.x, 4096.0f * x0[t]);
        ph1[t] = atan2f(v.y, 4096.0f * x1[t]);
    }
}

// ---------------- kernel 2: fused features + HMMA GEMM + argmin ----------
__device__ __forceinline__ void prefetch_chunk(uint32_t sdst, int ch, int tid) {
    const char* src = (const char*)g_B + (size_t)ch * CROWS * 256;
#pragma unroll
    for (int it = 0; it < 4; ++it) {
        const int i = tid + it * 256;       // 1024 uint4 total
        const int r = i >> 4, kq = i & 15;
        CP_ASYNC16(sdst + (uint32_t)r * KP_B + (uint32_t)kq * 16u,
                   src + (size_t)r * 256 + (size_t)kq * 16);
    }
    CP_COMMIT();
}

__global__ void __launch_bounds__(256, 2)
quant_kernel(const float* __restrict__ imu,
             const float* __restrict__ Wm,
             const float* __restrict__ bm,
             const float* __restrict__ Wp,
             const float* __restrict__ bp,
             const float* __restrict__ cb,
             float* __restrict__ out) {
    extern __shared__ char smem[];
    const uint32_t sbase = smem_to_u32(smem);
    const int tid = threadIdx.x;
    const int wid = tid >> 5;
    const int lane = tid & 31;
    const int pbase = blockIdx.x * MBLK;

    float* scn = (float*)(smem + SM_CN);
    float* rbv = (float*)(smem + SM_RBV);
    int* rbi = (int*)(smem + SM_RBI);
    int* sidx = (int*)(smem + SM_IDX);

    // start B pipeline before the heavy feature phase (buffers 0, 1)
    prefetch_chunk(sbase + SM_B0, 0, tid);
    prefetch_chunk(sbase + SM_B0 + 17408u, 1, tid);

    for (int i = tid; i < NC; i += 256) scn[i] = g_cn[i];

    // ---- features for 128 positions -> SMEM A (bf16 hi|lo)
    if (tid < MBLK) {
        const int p = pbase + tid;
        const int b = p >> 12;
        const int t = p & (TT - 1);

        const float* xb = imu + (size_t)b * CC * TT + t;
        float xc[9];
#pragma unroll
        for (int c = 0; c < 9; ++c) xc[c] = xb[c * TT];

        const float* phb = g_phase + (size_t)b * CC * TT + t;
        float pm = 0.0f;
#pragma unroll
        for (int c = 0; c < 9; ++c) pm += phb[c * TT];
        pm *= (1.0f / 9.0f);
        float sp, cp;
        sincosf(pm, &sp, &cp);
        out[OFF_PH + p] = pm;

        float f[64];
#pragma unroll
        for (int i = 0; i < 32; ++i) {
            float a = bm[i];
#pragma unroll
            for (int c = 0; c < 9; ++c) a += Wm[i * 9 + c] * xc[c];
            f[i] = a;
        }
        float comb[9];
#pragma unroll
        for (int c = 0; c < 7; ++c) comb[c] = xc[c];
        comb[7] = cp;
        comb[8] = sp;
#pragma unroll
        for (int i = 0; i < 32; ++i) {
            float a = bp[i];
#pragma unroll
            for (int c = 0; c < 9; ++c) a += Wp[i * 9 + c] * comb[c];
            f[32 + i] = a;
        }

        uint32_t* row32 = (uint32_t*)(smem + SM_A + (uint32_t)tid * KP_B);
#pragma unroll
        for (int q = 0; q < 32; ++q) {
            uint32_t hp, lp;
            split_pack(f[2 * q], f[2 * q + 1], hp, lp);
            row32[q] = hp;            // f_hi (bytes 0..127)
            row32[32 + q] = lp;       // f_lo (bytes 128..255)
        }
    }
    __syncthreads();   // A + cn visible

    // ---- GEMM + argmin. Warp tile m32 x n32: 4 m-warps x 2 n-warps.
    const int wrow = wid & 3;
    const int wcol = wid >> 2;
    const int m0 = wrow * 32;

    float best[4];
    int bidx[4];
#pragma unroll
    for (int i = 0; i < 4; ++i) { best[i] = CUDART_INF_F; bidx[i] = 0; }

    const int mgrp = lane >> 3;     // 0..3
    const int mrow = lane & 7;
    const uint32_t a_base = sbase + SM_A
        + (uint32_t)(m0 + mrow + 8 * (mgrp & 1)) * KP_B
        + (uint32_t)(8 * (mgrp >> 1)) * 2u;
    const uint32_t b_base = (uint32_t)(wcol * 32) * KP_B
        + (uint32_t)(8 * (mgrp >> 1) + mrow) * KP_B
        + (uint32_t)(8 * (mgrp & 1)) * 2u;

    // ---- A fragments register-resident: [mt][kquad][hi/lo][4] = 64 regs
    uint32_t afr[2][4][2][4];
#pragma unroll
    for (int mt = 0; mt < 2; ++mt)
#pragma unroll
        for (int kq = 0; kq < 4; ++kq) {
            const uint32_t ab = a_base + (uint32_t)mt * (16u * KP_B)
                                + (uint32_t)kq * 32u;
            LDSM_X4(afr[mt][kq][0][0], afr[mt][kq][0][1],
                    afr[mt][kq][0][2], afr[mt][kq][0][3], ab);
            LDSM_X4(afr[mt][kq][1][0], afr[mt][kq][1][1],
                    afr[mt][kq][1][2], afr[mt][kq][1][3], ab + 128u);
        }

#pragma unroll 1
    for (int ch = 0; ch < 8; ++ch) {
        if (ch < 7) { CP_WAIT(1); } else { CP_WAIT(0); }
        __syncthreads();            // chunk ch buffer complete; all warps past ch-1

        // prefetch ch+2 into ring buffer (ch+2)%3 — not read until chunk ch+2
        if (ch < 6)
            prefetch_chunk(sbase + SM_B0 + (uint32_t)((ch + 2) % 3) * 17408u,
                           ch + 2, tid);

        const uint32_t sB = sbase + SM_B0 + (uint32_t)(ch % 3) * 17408u;

        float acc[2][4][4];
#pragma unroll
        for (int mt = 0; mt < 2; ++mt)
#pragma unroll
            for (int j = 0; j < 4; ++j)
#pragma unroll
                for (int q = 0; q < 4; ++q) acc[mt][j][q] = 0.0f;

        // acc += A_hi*B_hi + A_lo*B_hi + A_hi*B_lo  (4 k-quads of 16)
#pragma unroll
        for (int kq = 0; kq < 4; ++kq) {
            const uint32_t koff = (uint32_t)kq * 32u;
            {   // n-tile 0
                uint32_t bh[4], bl[4];
                LDSM_X4(bh[0], bh[1], bh[2], bh[3], sB + b_base + koff);
                LDSM_X4(bl[0], bl[1], bl[2], bl[3], sB + b_base + 128u + koff);
                MMA16816(acc[0][0], afr[0][kq][0], bh[0], bh[1]);
                MMA16816(acc[0][1], afr[0][kq][0], bh[2], bh[3]);
                MMA16816(acc[1][0], afr[1][kq][0], bh[0], bh[1]);
                MMA16816(acc[1][1], afr[1][kq][0], bh[2], bh[3]);
                MMA16816(acc[0][0], afr[0][kq][1], bh[0], bh[1]);
                MMA16816(acc[0][1], afr[0][kq][1], bh[2], bh[3]);
                MMA16816(acc[1][0], afr[1][kq][1], bh[0], bh[1]);
                MMA16816(acc[1][1], afr[1][kq][1], bh[2], bh[3]);
                MMA16816(acc[0][0], afr[0][kq][0], bl[0], bl[1]);
                MMA16816(acc[0][1], afr[0][kq][0], bl[2], bl[3]);
                MMA16816(acc[1][0], afr[1][kq][0], bl[0], bl[1]);
                MMA16816(acc[1][1], afr[1][kq][0], bl[2], bl[3]);
            }
            {   // n-tile 1
                uint32_t bh[4], bl[4];
                LDSM_X4(bh[0], bh[1], bh[2], bh[3],
                        sB + b_base + 16u * KP_B + koff);
                LDSM_X4(bl[0], bl[1], bl[2], bl[3],
                        sB + b_base + 16u * KP_B + 128u + koff);
                MMA16816(acc[0][2], afr[0][kq][0], bh[0], bh[1]);
                MMA16816(acc[0][3], afr[0][kq][0], bh[2], bh[3]);
                MMA16816(acc[1][2], afr[1][kq][0], bh[0], bh[1]);
                MMA16816(acc[1][3], afr[1][kq][0], bh[2], bh[3]);
                MMA16816(acc[0][2], afr[0][kq][1], bh[0], bh[1]);
                MMA16816(acc[0][3], afr[0][kq][1], bh[2], bh[3]);
                MMA16816(acc[1][2], afr[1][kq][1], bh[0], bh[1]);
                MMA16816(acc[1][3], afr[1][kq][1], bh[2], bh[3]);
                MMA16816(acc[0][2], afr[0][kq][0], bl[0], bl[1]);
                MMA16816(acc[0][3], afr[0][kq][0], bl[2], bl[3]);
                MMA16816(acc[1][2], afr[1][kq][0], bl[0], bl[1]);
                MMA16816(acc[1][3], afr[1][kq][0], bl[2], bl[3]);
            }
        }

        // running argmin (codes strictly increasing -> first-min kept)
#pragma unroll
        for (int mt = 0; mt < 2; ++mt)
#pragma unroll
            for (int j = 0; j < 4; ++j) {
                const int c0 = ch * CROWS + wcol * 32 + (j >> 1) * 16
                               + (j & 1) * 8 + (lane & 3) * 2;
                const float n0v = scn[c0], n1v = scn[c0 + 1];
                const float d0 = fmaf(-2.0f, acc[mt][j][0], n0v);
                const float d1 = fmaf(-2.0f, acc[mt][j][1], n1v);
                const float d2 = fmaf(-2.0f, acc[mt][j][2], n0v);
                const float d3 = fmaf(-2.0f, acc[mt][j][3], n1v);
                const int s0 = 2 * mt, s1 = 2 * mt + 1;
                if (d0 < best[s0]) { best[s0] = d0; bidx[s0] = c0; }
                if (d1 < best[s0]) { best[s0] = d1; bidx[s0] = c0 + 1; }
                if (d2 < best[s1]) { best[s1] = d2; bidx[s1] = c0; }
                if (d3 < best[s1]) { best[s1] = d3; bidx[s1] = c0 + 1; }
            }
    }

    // reduce across the 4 lanes sharing each row (quad)
#pragma unroll
    for (int off = 1; off <= 2; off <<= 1) {
#pragma unroll
        for (int s = 0; s < 4; ++s) {
            float ob = __shfl_xor_sync(0xffffffffu, best[s], off);
            int oi = __shfl_xor_sync(0xffffffffu, bidx[s], off);
            if (ob < best[s] || (ob == best[s] && oi < bidx[s])) {
                best[s] = ob; bidx[s] = oi;
            }
        }
    }
    if ((lane & 3) == 0) {
        const int r = lane >> 2;
#pragma unroll
        for (int mt = 0; mt < 2; ++mt)
#pragma unroll
            for (int h = 0; h < 2; ++h) {
                const int row = m0 + mt * 16 + 8 * h + r;
                rbv[row * 2 + wcol] = best[2 * mt + h];
                rbi[row * 2 + wcol] = bidx[2 * mt + h];
            }
    }
    __syncthreads();

    // cross-nwarp reduce: one thread per row
    if (tid < MBLK) {
        float bv = rbv[tid * 2];
        int bi = rbi[tid * 2];
        const float ov = rbv[tid * 2 + 1];
        const int oi = rbi[tid * 2 + 1];
        if (ov < bv || (ov == bv && oi < bi)) { bv = ov; bi = oi; }
        sidx[tid] = bi;
        out[OFF_IDX + pbase + tid] = (float)bi;
    }
    __syncthreads();

    // quantized rows from fp32 codebook (L2-hot)
    const float4* cb4 = (const float4*)cb;
    for (int q = tid; q < MBLK * (CD / 4); q += 256) {
        const int pos = q >> 4;
        const int w = q & 15;
        ((float4*)(out + (size_t)(pbase + pos) * CD))[w] =
            cb4[(size_t)sidx[pos] * (CD / 4) + w];
    }
}

// ---------------- launch ----------------
extern "C" void kernel_launch(void* const* d_in, const int* in_sizes, int n_in,
                              void* d_out, int out_size) {
    const float* imu = (const float*)d_in[0];
    const float* Wm  = (const float*)d_in[1];
    const float* bm  = (const float*)d_in[2];
    const float* Wp  = (const float*)d_in[3];
    const float* bp  = (const float*)d_in[4];
    const float* cb  = (const float*)d_in[5];
    float* out = (float*)d_out;

    const int fft_smem = 2 * TT * (int)sizeof(float2);  // 64 KB
    cudaFuncSetAttribute(fft_conv_kernel,
                         cudaFuncAttributeMaxDynamicSharedMemorySize, fft_smem);
    fft_conv_kernel<<<NPAIR + NC / 16, 512, fft_smem>>>(imu, cb);

    cudaFuncSetAttribute(quant_kernel,
                         cudaFuncAttributeMaxDynamicSharedMemorySize, SMEMSZ);
    quant_kernel<<<(BB * TT) / MBLK, 256, SMEMSZ>>>(imu, Wm, bm, Wp, bp, cb, out);
}